// round 13
// baseline (speedup 1.0000x reference)
#include <cuda_runtime.h>
#include <cuda_bf16.h>
#include <cstdint>

// ---------------- problem constants ----------------
constexpr int cB    = 256;
constexpr int cNPG  = 28;
constexpr int cMAXN = 32;
constexpr int cD    = 128;
constexpr int cN    = 2 * cB * cNPG;   // 14336 nodes
constexpr int cE    = 2 * cB * 64;     // 32768 edges

// ---------------- scratch (device globals) ----------------
__device__ float g_h[cN * cD];
__device__ float g_e[cE * cD];
__device__ float g_agg[cN * cD];
__device__ float g_em[cE * cD];
__device__ float g_tqc[cB * 2 * cMAXN * 64];
__device__ float g_plan[cB * cMAXN * cMAXN];
__device__ float g_pre[cN * 1024];     // [h@W1a | h@W1b | h@R1a | h@R1b]
__device__ float g_epre[cE * 512];     // [e@W1c + b1m | e@R1c + b1r]
// bf16 hi/lo pre-split inputs (swizzled 256B rows): hi block then lo block
__device__ __align__(256) unsigned char g_hsp[cN * 512];
__device__ __align__(256) unsigned char g_esp[cE * 512];

// weight scratch (bf16 hi then lo per matrix)
__device__ __align__(256) unsigned char g_wt[1441792];
constexpr size_t OFF_UPD1  = 0;        // 256x256 : 262144 B
constexpr size_t OFF_MSG2  = 262144;   // 256x128 : 131072 B
constexpr size_t OFF_RMSG2 = 393216;
constexpr size_t OFF_UPD2  = 524288;
constexpr size_t OFF_WCAT  = 655360;   // 128x1024: 524288 B
constexpr size_t OFF_WEC   = 1179648;  // 128x512 : 262144 B

// ---------------- smem layouts ----------------
// pre_gemm: X hi 8K | X lo 8K | W bufs 2x16K
constexpr int SMEM_PRE = 49152;
// edge2: H hi 16K | H lo 16K | W2 bufs 2x16K | idx
constexpr int e2W2B = 32768;
constexpr int e2IDX = 65536;
constexpr int SMEM_EDGE2 = 65792;
// upd
constexpr int uX_HI = 0;
constexpr int uX_LO = 16384;
constexpr int uWB   = 32768;
constexpr int uW2B  = 65536;
constexpr int SMEM_UPD = 98304;

// ---------------- PTX helpers (portable) ----------------
__device__ __forceinline__ uint32_t smem_u32(const void* p) {
    uint32_t a;
    asm("{ .reg .u64 t; cvta.to.shared.u64 t, %1; cvt.u32.u64 %0, t; }" : "=r"(a) : "l"(p));
    return a;
}
__device__ __forceinline__ void ldsm_x4(uint32_t* r, uint32_t addr) {
    asm volatile("ldmatrix.sync.aligned.m8n8.x4.shared.b16 {%0,%1,%2,%3}, [%4];"
        : "=r"(r[0]), "=r"(r[1]), "=r"(r[2]), "=r"(r[3]) : "r"(addr));
}
__device__ __forceinline__ void ldsm_x4t(uint32_t* r, uint32_t addr) {
    asm volatile("ldmatrix.sync.aligned.m8n8.x4.trans.shared.b16 {%0,%1,%2,%3}, [%4];"
        : "=r"(r[0]), "=r"(r[1]), "=r"(r[2]), "=r"(r[3]) : "r"(addr));
}
__device__ __forceinline__ void mma16816(float* d, const uint32_t* a, const uint32_t* b) {
    asm volatile(
        "mma.sync.aligned.m16n8k16.row.col.f32.bf16.bf16.f32 "
        "{%0,%1,%2,%3}, {%4,%5,%6,%7}, {%8,%9}, {%0,%1,%2,%3};"
        : "+f"(d[0]), "+f"(d[1]), "+f"(d[2]), "+f"(d[3])
        : "r"(a[0]), "r"(a[1]), "r"(a[2]), "r"(a[3]), "r"(b[0]), "r"(b[1]));
}
__device__ __forceinline__ void cp16(uint32_t dst, const void* src) {
    asm volatile("cp.async.cg.shared.global [%0], [%1], 16;" :: "r"(dst), "l"(src));
}
#define CP_COMMIT() asm volatile("cp.async.commit_group;" ::: "memory")
#define CP_WAIT0()  asm volatile("cp.async.wait_group 0;" ::: "memory")

__device__ __forceinline__ uint32_t bf16_split2(float x0, float x1, uint32_t& lo_out) {
    __nv_bfloat16 h0 = __float2bfloat16(x0);
    __nv_bfloat16 h1 = __float2bfloat16(x1);
    __nv_bfloat16 l0 = __float2bfloat16(x0 - __bfloat162float(h0));
    __nv_bfloat16 l1 = __float2bfloat16(x1 - __bfloat162float(h1));
    lo_out = (uint32_t)__bfloat16_as_ushort(l0) | ((uint32_t)__bfloat16_as_ushort(l1) << 16);
    return (uint32_t)__bfloat16_as_ushort(h0) | ((uint32_t)__bfloat16_as_ushort(h1) << 16);
}

__device__ __forceinline__ float warp_max(float v) {
#pragma unroll
    for (int o = 16; o > 0; o >>= 1) v = fmaxf(v, __shfl_xor_sync(0xffffffffu, v, o));
    return v;
}
__device__ __forceinline__ float warp_sum(float v) {
#pragma unroll
    for (int o = 16; o > 0; o >>= 1) v += __shfl_xor_sync(0xffffffffu, v, o);
    return v;
}

// ---------------- fused weight prep ----------------
__global__ void prep_all(const float* __restrict__ m1, const float* __restrict__ r1w,
                         const float* __restrict__ u1, const float* __restrict__ m2,
                         const float* __restrict__ r2w, const float* __restrict__ u2,
                         unsigned char* __restrict__ wt) {
    int idx = blockIdx.x * 256 + threadIdx.x;
    if (idx >= 360448) return;
    float x; unsigned short* d; int l, losz;
    if (idx < 65536) {
        l = idx; x = u1[l]; d = (unsigned short*)(wt + OFF_UPD1); losz = 65536;
    } else if (idx < 98304) {
        l = idx - 65536; x = m2[l]; d = (unsigned short*)(wt + OFF_MSG2); losz = 32768;
    } else if (idx < 131072) {
        l = idx - 98304; x = r2w[l]; d = (unsigned short*)(wt + OFF_RMSG2); losz = 32768;
    } else if (idx < 163840) {
        l = idx - 131072; x = u2[l]; d = (unsigned short*)(wt + OFF_UPD2); losz = 32768;
    } else if (idx < 294912) {
        l = idx - 163840;
        int k = l >> 10, n = l & 1023;
        if (n < 256)      x = m1[k * 256 + n];
        else if (n < 512) x = m1[(128 + k) * 256 + (n - 256)];
        else if (n < 768) x = r1w[k * 256 + (n - 512)];
        else              x = r1w[(128 + k) * 256 + (n - 768)];
        d = (unsigned short*)(wt + OFF_WCAT); losz = 131072;
    } else {
        l = idx - 294912;
        int k = l >> 9, n = l & 511;
        x = (n < 256) ? m1[(256 + k) * 256 + n] : r1w[(256 + k) * 256 + (n - 256)];
        d = (unsigned short*)(wt + OFF_WEC); losz = 65536;
    }
    __nv_bfloat16 hb = __float2bfloat16(x);
    __nv_bfloat16 lb = __float2bfloat16(x - __bfloat162float(hb));
    d[l]        = __bfloat16_as_ushort(hb);
    d[losz + l] = __bfloat16_as_ushort(lb);
}

// ---------------- split fp32 [R][128] -> swizzled bf16 hi/lo 256B rows ----------------
__global__ void __launch_bounds__(256) split_rows(const float* __restrict__ src,
                                                  unsigned char* __restrict__ hi,
                                                  unsigned char* __restrict__ lo, int nrows) {
    int idx = blockIdx.x * 256 + threadIdx.x;
    if (idx >= nrows * 64) return;
    int r = idx >> 6, j = idx & 63;
    float2 v = *(const float2*)&src[(size_t)r * 128 + 2 * j];
    uint32_t l, h = bf16_split2(v.x, v.y, l);
    uint32_t o = (uint32_t)r * 256 + (((uint32_t)(4 * j)) ^ ((uint32_t)(r & 7) << 4));
    *(uint32_t*)(hi + o) = h;
    *(uint32_t*)(lo + o) = l;
}

// ---------------- encoder ----------------
__global__ void __launch_bounds__(128) encode16(const float* __restrict__ x,
                                                const float* __restrict__ W,
                                                const float* __restrict__ bias, int which) {
    __shared__ float sW[32 * 128];
    __shared__ float sx[16][32];
    int tid = threadIdx.x;
    int r0 = blockIdx.x * 16;
    for (int i = tid; i < 4096; i += 128) sW[i] = W[i];
    for (int i = tid; i < 512; i += 128) sx[i >> 5][i & 31] = x[r0 * 32 + i];
    __syncthreads();
    float b = bias[tid];
    float* dst = (which == 0) ? g_h : g_e;
#pragma unroll 4
    for (int rr = 0; rr < 16; rr++) {
        float acc = b;
#pragma unroll
        for (int k = 0; k < 32; k++) acc = fmaf(sx[rr][k], sW[k * 128 + tid], acc);
        dst[(size_t)(r0 + rr) * 128 + tid] = acc;
    }
}

// ---------------- pre_gemm: [32 x 128] @ [128 x 128-slice] -> fp32 ----------------
// X from pre-split bf16 global (swizzled 256B rows). Slice col base = blockIdx.y*128.
__global__ void __launch_bounds__(256, 3) pre_gemm(
    const unsigned char* __restrict__ xhi, const unsigned char* __restrict__ xlo,
    const unsigned char* __restrict__ w, int wRowB, int wLoOff,
    float* __restrict__ dst, int dstStride,
    const float* __restrict__ biasA, const float* __restrict__ biasB) {
    extern __shared__ __align__(16) unsigned char smem[];
    const uint32_t sb = smem_u32(smem);
    const int tid = threadIdx.x, lane = tid & 31, wid = tid >> 5;
    const int r0 = blockIdx.x * 32;
    const int cbk = blockIdx.y;

    // X copy (hi 8K + lo 8K) — swizzle preserved byte-for-byte ((r0+r)&7 == r&7)
    for (int i = tid; i < 1024; i += 256) {
        int comp = i >> 9, t = i & 511;
        int r = t >> 4, cc = t & 15;
        cp16(sb + comp * 8192 + r * 256 + cc * 16,
             (comp ? xlo : xhi) + (size_t)(r0 + r) * 256 + cc * 16);
    }
    // W chunk 0 (32 k-rows x 128 cols, hi+lo)
    for (int i = tid; i < 1024; i += 256) {
        int comp = i >> 9, t = i & 511;
        int rr = t >> 4, cc = t & 15;
        cp16(sb + 16384 + comp * 8192 + rr * 256 + ((cc * 16) ^ ((rr & 7) << 4)),
             w + (size_t)comp * wLoOff + (size_t)rr * wRowB + cbk * 256 + cc * 16);
    }
    CP_COMMIT();

    const int rg = (wid & 1) << 4;          // 2 rowgroups of 16
    const int n0 = (wid >> 1) << 5;         // 4 colgroups of 32
    const int m_ = lane >> 3, r_ = lane & 7;
    const int arow = rg + ((m_ & 1) << 3) + r_;
    const int acol = (m_ >> 1) << 3;
    const int bRow = lane & 15, bAdd = (lane >> 4) << 3;
    const uint32_t aswz = (uint32_t)(arow & 7) << 4;
    const uint32_t bswz = (uint32_t)(bRow & 7) << 4;
    const uint32_t aHiB = sb + (uint32_t)arow * 256;
    const uint32_t aLoB = aHiB + 8192;

    float acc[4][4];
#pragma unroll
    for (int j = 0; j < 4; j++)
#pragma unroll
        for (int q = 0; q < 4; q++) acc[j][q] = 0.f;

    for (int c = 0; c < 4; c++) {
        CP_WAIT0();
        __syncthreads();
        if (c + 1 < 4) {
            const int nb = (c + 1) & 1;
            for (int i = tid; i < 1024; i += 256) {
                int comp = i >> 9, t = i & 511;
                int rr = t >> 4, cc = t & 15;
                cp16(sb + 16384 + nb * 16384 + comp * 8192 + rr * 256 + ((cc * 16) ^ ((rr & 7) << 4)),
                     w + (size_t)comp * wLoOff + (size_t)((c + 1) * 32 + rr) * wRowB + cbk * 256 + cc * 16);
            }
            CP_COMMIT();
        }
        const uint32_t wb = sb + 16384 + (c & 1) * 16384;
#pragma unroll
        for (int kt = 0; kt < 2; kt++) {
            int kg = c * 32 + kt * 16;
            uint32_t aHi[4], aLo[4];
            uint32_t ac = ((uint32_t)((acol + kg) * 2)) ^ aswz;
            ldsm_x4(aHi, aHiB + ac);
            ldsm_x4(aLo, aLoB + ac);
            uint32_t bb = wb + (uint32_t)(kt * 16 + bRow) * 256;
#pragma unroll
            for (int j = 0; j < 2; j++) {
                uint32_t cbyte = ((uint32_t)((n0 + bAdd + j * 16) * 2)) ^ bswz;
                uint32_t bh[4], bl[4];
                ldsm_x4t(bh, bb + cbyte);
                ldsm_x4t(bl, bb + 8192 + cbyte);
                mma16816(acc[2 * j],     aHi, bh);
                mma16816(acc[2 * j + 1], aHi, bh + 2);
                mma16816(acc[2 * j],     aHi, bl);
                mma16816(acc[2 * j + 1], aHi, bl + 2);
                mma16816(acc[2 * j],     aLo, bh);
                mma16816(acc[2 * j + 1], aLo, bh + 2);
            }
        }
    }
    // epilogue
    const float* bias = nullptr;
    if (biasA) {
        int half = gridDim.y >> 1;
        bias = (cbk < half ? biasA : biasB) + (cbk % half) * 128;
    }
    const int cb_ = n0 + (lane & 3) * 2;
    const int r1 = rg + (lane >> 2);
#pragma unroll
    for (int j = 0; j < 4; j++) {
        int cc = cb_ + j * 8;
        float b0 = bias ? __ldg(bias + cc) : 0.f;
        float b1v = bias ? __ldg(bias + cc + 1) : 0.f;
        size_t o0 = (size_t)(r0 + r1) * dstStride + cbk * 128 + cc;
        size_t o1 = (size_t)(r0 + r1 + 8) * dstStride + cbk * 128 + cc;
        dst[o0]     = acc[j][0] + b0;
        dst[o0 + 1] = acc[j][1] + b1v;
        dst[o1]     = acc[j][2] + b0;
        dst[o1 + 1] = acc[j][3] + b1v;
    }
}

// ---------------- edge2: gather-add-relu + stage2 GEMM, msg then rmsg ----------------
template <int MODE>
__global__ void __launch_bounds__(256, 3) edge2(
    const int* __restrict__ from_idx, const int* __restrict__ to_idx,
    const unsigned char* __restrict__ wt,
    const float* __restrict__ b2m, const float* __restrict__ b2r) {
    extern __shared__ __align__(16) unsigned char smem[];
    const uint32_t sb = smem_u32(smem);
    const int tid = threadIdx.x, lane = tid & 31, wid = tid >> 5;
    const int e0 = blockIdx.x * 32;
    int* sF = (int*)(smem + e2IDX);
    int* sT = sF + 32;
    if (tid < 32) { sF[tid] = from_idx[e0 + tid]; sT[tid] = to_idx[e0 + tid]; }
    __syncthreads();

    const int rg = (wid & 1) << 4;
    const int n2 = (wid >> 1) << 5;
    const int m_ = lane >> 3, r_ = lane & 7;
    const int arow = rg + ((m_ & 1) << 3) + r_;
    const int acol = (m_ >> 1) << 3;
    const int bRow = lane & 15, bAdd = (lane >> 4) << 3;
    const uint32_t aswz = (uint32_t)(arow & 7) << 4;
    const uint32_t bswz = (uint32_t)(bRow & 7) << 4;
    const uint32_t aHiB = sb + (uint32_t)arow * 512;
    const uint32_t aLoB = aHiB + 16384;

#pragma unroll
    for (int ph = 0; ph < 2; ph++) {
        const unsigned char* w2t = wt + (ph ? OFF_RMSG2 : OFF_MSG2);
        const float* b2 = ph ? b2r : b2m;
        if (ph) __syncthreads();
        for (int i = tid; i < 1024; i += 256) {
            int comp = i >> 9, rr = (i >> 4) & 31, cc = i & 15;
            cp16(sb + e2W2B + comp * 8192 + rr * 256 + ((cc * 16) ^ ((rr & 7) << 4)),
                 w2t + (size_t)comp * 65536 + (size_t)rr * 256 + cc * 16);
        }
        CP_COMMIT();
        for (int i = tid; i < 2048; i += 256) {
            int r = i >> 6, c4 = (i & 63) << 2;
            int ia = ph ? sT[r] : sF[r];
            int ib = ph ? sF[r] : sT[r];
            const float4 fa = *(const float4*)&g_pre[(size_t)ia * 1024 + ph * 512 + c4];
            const float4 fb = *(const float4*)&g_pre[(size_t)ib * 1024 + ph * 512 + 256 + c4];
            const float4 fe = *(const float4*)&g_epre[(size_t)(e0 + r) * 512 + ph * 256 + c4];
            float v0 = fmaxf(fa.x + fb.x + fe.x, 0.f);
            float v1 = fmaxf(fa.y + fb.y + fe.y, 0.f);
            float v2 = fmaxf(fa.z + fb.z + fe.z, 0.f);
            float v3 = fmaxf(fa.w + fb.w + fe.w, 0.f);
            uint32_t lo0, hi0 = bf16_split2(v0, v1, lo0);
            uint32_t lo1, hi1 = bf16_split2(v2, v3, lo1);
            uint32_t o = (uint32_t)r * 512 + (((uint32_t)(c4 * 2)) ^ ((uint32_t)(r & 7) << 4));
            *(uint32_t*)(smem + o)             = hi0;
            *(uint32_t*)(smem + o + 4)         = hi1;
            *(uint32_t*)(smem + 16384 + o)     = lo0;
            *(uint32_t*)(smem + 16384 + o + 4) = lo1;
        }
        float acc2[4][4];
#pragma unroll
        for (int j = 0; j < 4; j++)
#pragma unroll
            for (int q = 0; q < 4; q++) acc2[j][q] = 0.f;
        for (int c = 0; c < 8; c++) {
            CP_WAIT0();
            __syncthreads();
            if (c + 1 < 8) {
                const int nb = (c + 1) & 1;
                for (int i = tid; i < 1024; i += 256) {
                    int comp = i >> 9, rr = (i >> 4) & 31, cc = i & 15;
                    cp16(sb + e2W2B + nb * 16384 + comp * 8192 + rr * 256 + ((cc * 16) ^ ((rr & 7) << 4)),
                         w2t + (size_t)comp * 65536 + (size_t)((c + 1) * 32 + rr) * 256 + cc * 16);
                }
                CP_COMMIT();
            }
            const uint32_t wb2 = sb + e2W2B + (c & 1) * 16384;
#pragma unroll
            for (int kt = 0; kt < 2; kt++) {
                int kg = c * 32 + kt * 16;
                uint32_t aHi[4], aLo[4];
                uint32_t ac = ((uint32_t)((acol + kg) * 2)) ^ aswz;
                ldsm_x4(aHi, aHiB + ac);
                ldsm_x4(aLo, aLoB + ac);
                uint32_t bb = wb2 + (uint32_t)(kt * 16 + bRow) * 256;
#pragma unroll
                for (int j = 0; j < 2; j++) {
                    uint32_t cbyte = ((uint32_t)((n2 + bAdd + j * 16) * 2)) ^ bswz;
                    uint32_t bh[4], bl[4];
                    ldsm_x4t(bh, bb + cbyte);
                    ldsm_x4t(bl, bb + 8192 + cbyte);
                    mma16816(acc2[2 * j],     aHi, bh);
                    mma16816(acc2[2 * j + 1], aHi, bh + 2);
                    mma16816(acc2[2 * j],     aHi, bl);
                    mma16816(acc2[2 * j + 1], aHi, bl + 2);
                    mma16816(acc2[2 * j],     aLo, bh);
                    mma16816(acc2[2 * j + 1], aLo, bh + 2);
                }
            }
        }
        const int cb_ = n2 + (lane & 3) * 2;
        const int r1 = rg + (lane >> 2);
#pragma unroll
        for (int j = 0; j < 4; j++) {
            int cc = cb_ + j * 8;
            float b0 = __ldg(b2 + cc), b1v = __ldg(b2 + cc + 1);
            float v00 = acc2[j][0] + b0, v01 = acc2[j][1] + b1v;
            float v10 = acc2[j][2] + b0, v11 = acc2[j][3] + b1v;
            if (MODE == 0) {
                int nA = ph ? sF[r1] : sT[r1];
                int nB = ph ? sF[r1 + 8] : sT[r1 + 8];
                atomicAdd(&g_agg[(size_t)nA * cD + cc],     v00);
                atomicAdd(&g_agg[(size_t)nA * cD + cc + 1], v01);
                atomicAdd(&g_agg[(size_t)nB * cD + cc],     v10);
                atomicAdd(&g_agg[(size_t)nB * cD + cc + 1], v11);
            } else {
                float* d0 = &g_em[(size_t)(e0 + r1) * cD + cc];
                float* d1 = &g_em[(size_t)(e0 + r1 + 8) * cD + cc];
                if (ph == 0) {
                    d0[0] = v00; d0[1] = v01;
                    d1[0] = v10; d1[1] = v11;
                } else {
                    d0[0] += v00; d0[1] += v01;
                    d1[0] += v10; d1[1] += v11;
                }
            }
        }
    }
}

// ---------------- run_mlp (used by upd only) ----------------
template <int K1, int XST, int XHI, int XLO, int WB, int W2B>
__device__ __forceinline__ void run_mlp(
    unsigned char* smem, uint32_t sb,
    const unsigned char* __restrict__ w1t, const float* __restrict__ b1p,
    const unsigned char* __restrict__ w2t,
    int tid, int lane, int wid, float out[4][4]) {
    const int rg = (wid & 1) << 4;
    const int n0 = (wid >> 1) << 6;
    const int n2 = (wid >> 1) << 5;
    const int m_ = lane >> 3, r_ = lane & 7;
    const int arow = rg + ((m_ & 1) << 3) + r_;
    const int acol = (m_ >> 1) << 3;
    const int bRow = lane & 15;
    const int bAdd = (lane >> 4) << 3;
    const uint32_t aswz = (uint32_t)(arow & 7) << 4;
    const uint32_t aHiB = sb + XHI + (uint32_t)arow * XST;
    const uint32_t aLoB = sb + XLO + (uint32_t)arow * XST;
    const uint32_t bswz = (uint32_t)(bRow & 7) << 4;

    float acc[8][4];
#pragma unroll
    for (int j = 0; j < 8; j++)
#pragma unroll
        for (int q = 0; q < 4; q++) acc[j][q] = 0.f;

    constexpr int NC1 = K1 / 32;
    for (int i = tid; i < 2048; i += 256) {
        int comp = i >> 10, rr = (i >> 5) & 31, cc = i & 31;
        cp16(sb + WB + comp * 16384 + rr * 512 + ((cc * 16) ^ ((rr & 7) << 4)),
             w1t + (size_t)comp * (K1 * 512) + (size_t)rr * 512 + cc * 16);
    }
    CP_COMMIT();

    for (int c = 0; c < NC1; c++) {
        CP_WAIT0();
        __syncthreads();
        if (c + 1 < NC1) {
            const int nb = (c + 1) & 1;
            for (int i = tid; i < 2048; i += 256) {
                int comp = i >> 10, rr = (i >> 5) & 31, cc = i & 31;
                cp16(sb + WB + nb * 32768 + comp * 16384 + rr * 512 + ((cc * 16) ^ ((rr & 7) << 4)),
                     w1t + (size_t)comp * (K1 * 512) + (size_t)((c + 1) * 32 + rr) * 512 + cc * 16);
            }
            CP_COMMIT();
        }
        const uint32_t wb1 = sb + WB + (c & 1) * 32768;
#pragma unroll
        for (int kt = 0; kt < 2; kt++) {
            int kg = c * 32 + kt * 16;
            uint32_t aHi[4], aLo[4];
            uint32_t ac = ((uint32_t)((acol + kg) * 2)) ^ aswz;
            ldsm_x4(aHi, aHiB + ac);
            ldsm_x4(aLo, aLoB + ac);
            uint32_t bb = wb1 + (uint32_t)(kt * 16 + bRow) * 512;
#pragma unroll
            for (int j = 0; j < 4; j++) {
                uint32_t cbyte = ((uint32_t)((n0 + bAdd + j * 16) * 2)) ^ bswz;
                uint32_t bh[4], bl[4];
                ldsm_x4t(bh, bb + cbyte);
                ldsm_x4t(bl, bb + 16384 + cbyte);
                mma16816(acc[2 * j],     aHi, bh);
                mma16816(acc[2 * j + 1], aHi, bh + 2);
                mma16816(acc[2 * j],     aHi, bl);
                mma16816(acc[2 * j + 1], aHi, bl + 2);
                mma16816(acc[2 * j],     aLo, bh);
                mma16816(acc[2 * j + 1], aLo, bh + 2);
            }
        }
    }
    __syncthreads();

    {
        int cb = n0 + (lane & 3) * 2;
        int r1 = rg + (lane >> 2);
        uint32_t s1 = (uint32_t)(r1 & 7) << 4;
#pragma unroll
        for (int j = 0; j < 8; j++) {
            int cc = cb + j * 8;
            float b0 = __ldg(b1p + cc), b1v = __ldg(b1p + cc + 1);
            float v00 = fmaxf(acc[j][0] + b0, 0.f), v01 = fmaxf(acc[j][1] + b1v, 0.f);
            float v10 = fmaxf(acc[j][2] + b0, 0.f), v11 = fmaxf(acc[j][3] + b1v, 0.f);
            uint32_t lo0, hi0 = bf16_split2(v00, v01, lo0);
            uint32_t lo1, hi1 = bf16_split2(v10, v11, lo1);
            uint32_t o1 = ((uint32_t)(cc * 2)) ^ s1;
            *(uint32_t*)(smem + WB + r1 * 512 + o1)               = hi0;
            *(uint32_t*)(smem + WB + 16384 + r1 * 512 + o1)       = lo0;
            *(uint32_t*)(smem + WB + (r1 + 8) * 512 + o1)         = hi1;
            *(uint32_t*)(smem + WB + 16384 + (r1 + 8) * 512 + o1) = lo1;
        }
    }

    float acc2[4][4];
#pragma unroll
    for (int j = 0; j < 4; j++)
#pragma unroll
        for (int q = 0; q < 4; q++) acc2[j][q] = 0.f;
    const uint32_t a2HiB = sb + WB + (uint32_t)arow * 512;
    const uint32_t a2LoB = a2HiB + 16384;

    for (int i = tid; i < 1024; i += 256) {
        int comp = i >> 9, rr = (i >> 4) & 31, cc = i & 15;
        cp16(sb + W2B + comp * 8192 + rr * 256 + ((cc * 16) ^ ((rr & 7) << 4)),
             w2t + (size_t)comp * 65536 + (size_t)rr * 256 + cc * 16);
    }
    CP_COMMIT();

    for (int c = 0; c < 8; c++) {
        CP_WAIT0();
        __syncthreads();
        if (c + 1 < 8) {
            const int nb = (c + 1) & 1;
            for (int i = tid; i < 1024; i += 256) {
                int comp = i >> 9, rr = (i >> 4) & 31, cc = i & 15;
                cp16(sb + W2B + nb * 16384 + comp * 8192 + rr * 256 + ((cc * 16) ^ ((rr & 7) << 4)),
                     w2t + (size_t)comp * 65536 + (size_t)((c + 1) * 32 + rr) * 256 + cc * 16);
            }
            CP_COMMIT();
        }
        const uint32_t wb2 = sb + W2B + (c & 1) * 16384;
#pragma unroll
        for (int kt = 0; kt < 2; kt++) {
            int kg = c * 32 + kt * 16;
            uint32_t aHi[4], aLo[4];
            uint32_t ac = ((uint32_t)((acol + kg) * 2)) ^ aswz;
            ldsm_x4(aHi, a2HiB + ac);
            ldsm_x4(aLo, a2LoB + ac);
            uint32_t bb = wb2 + (uint32_t)(kt * 16 + bRow) * 256;
#pragma unroll
            for (int j = 0; j < 2; j++) {
                uint32_t cbyte = ((uint32_t)((n2 + bAdd + j * 16) * 2)) ^ bswz;
                uint32_t bh[4], bl[4];
                ldsm_x4t(bh, bb + cbyte);
                ldsm_x4t(bl, bb + 8192 + cbyte);
                mma16816(acc2[2 * j],     aHi, bh);
                mma16816(acc2[2 * j + 1], aHi, bh + 2);
                mma16816(acc2[2 * j],     aHi, bl);
                mma16816(acc2[2 * j + 1], aHi, bl + 2);
                mma16816(acc2[2 * j],     aLo, bh);
                mma16816(acc2[2 * j + 1], aLo, bh + 2);
            }
        }
    }
    __syncthreads();
#pragma unroll
    for (int j = 0; j < 4; j++)
#pragma unroll
        for (int q = 0; q < 4; q++) out[j][q] = acc2[j][q];
}

// ---------------- upd kernel: h += mlp([agg, h]) ----------------
__global__ void __launch_bounds__(256, 2) upd_mlp(
    const unsigned char* __restrict__ wt,
    const float* __restrict__ b1p, const float* __restrict__ b2p) {
    extern __shared__ __align__(16) unsigned char smem[];
    const uint32_t sb = smem_u32(smem);
    const int tid = threadIdx.x, lane = tid & 31, wid = tid >> 5;
    const int e0 = blockIdx.x * 32;

    for (int i = tid; i < 2048; i += 256) {
        int r = i >> 6, q = i & 63;
        int seg = q >> 5, c4 = (q & 31) << 2;
        const float* src = (seg == 0 ? g_agg : g_h) + (size_t)(e0 + r) * cD + c4;
        float4 v = *(const float4*)src;
        int col = seg * 128 + c4;
        uint32_t lo0, hi0 = bf16_split2(v.x, v.y, lo0);
        uint32_t lo1, hi1 = bf16_split2(v.z, v.w, lo1);
        uint32_t o = (uint32_t)r * 512 + (((uint32_t)(col * 2)) ^ ((uint32_t)(r & 7) << 4));
        *(uint32_t*)(smem + uX_HI + o)     = hi0;
        *(uint32_t*)(smem + uX_HI + o + 4) = hi1;
        *(uint32_t*)(smem + uX_LO + o)     = lo0;
        *(uint32_t*)(smem + uX_LO + o + 4) = lo1;
    }

    float oacc[4][4];
    run_mlp<256, 512, uX_HI, uX_LO, uWB, uW2B>(smem, sb, wt + OFF_UPD1, b1p,
                                               wt + OFF_UPD2, tid, lane, wid, oacc);

    const int rg = (wid & 1) << 4;
    const int n2 = (wid >> 1) << 5;
    const int cb = n2 + (lane & 3) * 2;
    const int r1 = rg + (lane >> 2);
#pragma unroll
    for (int j = 0; j < 4; j++) {
        int cc = cb + j * 8;
        float b0 = __ldg(b2p + cc), b1v = __ldg(b2p + cc + 1);
        g_h[(size_t)(e0 + r1) * cD + cc]         += oacc[j][0] + b0;
        g_h[(size_t)(e0 + r1) * cD + cc + 1]     += oacc[j][1] + b1v;
        g_h[(size_t)(e0 + r1 + 8) * cD + cc]     += oacc[j][2] + b0;
        g_h[(size_t)(e0 + r1 + 8) * cD + cc + 1] += oacc[j][3] + b1v;
    }
}

// ---------------- SK head ----------------
__global__ void __launch_bounds__(256) sk_kernel(
    const float* __restrict__ w1p, const float* __restrict__ b1p,
    const float* __restrict__ w2p, const float* __restrict__ b2p,
    const int* __restrict__ qs, const int* __restrict__ cs) {
    int t = threadIdx.x;
    int lr = t >> 6, j = t & 63;
    int row = blockIdx.x * 4 + lr;
    int b = row >> 6, sp = row & 63, s = sp >> 5, p = sp & 31;
    __shared__ float sx[4][128];
    __shared__ float sh[4][64];
    {
        bool valid = p < cNPG;
        int node = (b * 2 + s) * cNPG + p;
        sx[lr][j]      = valid ? g_h[node * cD + j]      : 0.f;
        sx[lr][j + 64] = valid ? g_h[node * cD + j + 64] : 0.f;
    }
    __syncthreads();
    float a = b1p[j];
#pragma unroll
    for (int k = 0; k < 128; k++) a = fmaf(sx[lr][k], w1p[k * 64 + j], a);
    sh[lr][j] = fmaxf(a, 0.f);
    __syncthreads();
    float o = b2p[j];
#pragma unroll
    for (int k = 0; k < 64; k++) o = fmaf(sh[lr][k], w2p[k * 64 + j], o);
    int size = (s == 0) ? qs[b] : cs[b];
    if (p >= size) o = 0.f;
    g_tqc[row * 64 + j] = o;
}

// ---------------- node scores + Sinkhorn ----------------
__global__ void __launch_bounds__(1024) node_plan_kernel() {
    int b = blockIdx.x;
    int tid = threadIdx.x;
    __shared__ float smq[32][65];
    __shared__ float smc[32][65];
    __shared__ float la[32 * 33];
    for (int idx = tid; idx < 2048; idx += 1024) {
        int r = idx >> 6, d = idx & 63;
        smq[r][d] = g_tqc[b * 4096 + idx];
        smc[r][d] = g_tqc[b * 4096 + 2048 + idx];
    }
    __syncthreads();
    int q = tid >> 5, c = tid & 31;
    float v = 0.f;
#pragma unroll
    for (int d = 0; d < 64; d++) v = fmaf(smq[q][d], smc[c][d], v);
    v *= 10.f;
    {
        float m = warp_max(v);
        float sum = warp_sum(__expf(v - m));
        v -= m + __logf(sum);
        la[q * 33 + c] = v;
        __syncthreads();
        float u = la[c * 33 + q];
        float s = warp_sum(__expf(u));
        u -= __logf(s);
        la[c * 33 + q] = u;
        __syncthreads();
        v = la[q * 33 + c];
    }
    for (int it = 1; it < 20; it++) {
        float s = warp_sum(__expf(v));
        v -= __logf(s);
        la[q * 33 + c] = v;
        __syncthreads();
        float u = la[c * 33 + q];
        s = warp_sum(__expf(u));
        u -= __logf(s);
        la[c * 33 + q] = u;
        __syncthreads();
        v = la[q * 33 + c];
    }
    g_plan[b * 1024 + q * 32 + c] = __expf(v);
}

// ---------------- node alignment ----------------
__global__ void __launch_bounds__(256) node_align_kernel(float* __restrict__ out) {
    int b = blockIdx.x, tid = threadIdx.x;
    __shared__ float sp_[32 * 32];
    __shared__ float scn[32][128];
    __shared__ float red[8];
    for (int idx = tid; idx < 1024; idx += 256) sp_[idx] = g_plan[b * 1024 + idx];
    for (int idx = tid; idx < 4096; idx += 256) {
        int p = idx >> 7, d = idx & 127;
        scn[p][d] = (p < cNPG) ? g_h[((b * 2 + 1) * cNPG + p) * cD + d] : 0.f;
    }
    __syncthreads();
    float local = 0.f;
    for (int idx = tid; idx < 4096; idx += 256) {
        int q = idx >> 7, d = idx & 127;
        float pc = 0.f;
#pragma unroll
        for (int c = 0; c < 32; c++) pc = fmaf(sp_[q * 32 + c], scn[c][d], pc);
        float qv = (q < cNPG) ? g_h[((b * 2) * cNPG + q) * cD + d] : 0.f;
        local += fmaxf(qv - pc, 0.f);
    }
    local = warp_sum(local);
    if ((tid & 31) == 0) red[tid >> 5] = local;
    __syncthreads();
    if (tid == 0) {
        float tot = 0.f;
        for (int i = 0; i < 8; i++) tot += red[i];
        out[b] = -tot;
    }
}

// ---------------- edge kron + Sinkhorn + alignment ----------------
__global__ void __launch_bounds__(1024) edge_align_kernel(
    const int* __restrict__ from_idx, const int* __restrict__ to_idx,
    float* __restrict__ out) {
    int b = blockIdx.x, tid = threadIdx.x;
    __shared__ float T[32 * 32];
    __shared__ float la[64][65];
    __shared__ int qf[64], qt[64], cf[64], ct[64];
    __shared__ float red[32];

    T[tid & 1023] = g_plan[b * 1024 + (tid & 1023)];
    if (tid < 64) {
        qf[tid] = from_idx[b * 128 + tid] % cNPG;
        qt[tid] = to_idx[b * 128 + tid] % cNPG;
        cf[tid] = from_idx[b * 128 + 64 + tid] % cNPG;
        ct[tid] = to_idx[b * 128 + 64 + tid] % cNPG;
    }
    __syncthreads();
    for (int idx = tid; idx < 4096; idx += 1024) {
        int i = idx >> 6, j = idx & 63;
        float s = T[qf[i] * 32 + cf[j]] * T[qt[i] * 32 + ct[j]]
                + T[qf[i] * 32 + ct[j]] * T[qt[i] * 32 + cf[j]];
        la[i][j] = s * 10.f;
    }
    __syncthreads();
    int w = tid >> 5, l = tid & 31;
    for (int it = 0; it < 20; it++) {
#pragma unroll
        for (int rr_ = 0; rr_ < 2; rr_++) {
            int rr = w + rr_ * 32;
            float v0 = la[rr][l], v1 = la[rr][l + 32];
            float s = warp_sum(__expf(v0) + __expf(v1));
            float lse = __logf(s);
            la[rr][l] = v0 - lse;
            la[rr][l + 32] = v1 - lse;
        }
        __syncthreads();
#pragma unroll
        for (int cc_ = 0; cc_ < 2; cc_++) {
            int cc = w + cc_ * 32;
            float v0 = la[l][cc], v1 = la[l + 32][cc];
            float s = warp_sum(__expf(v0) + __expf(v1));
            float lse = __logf(s);
            la[l][cc] = v0 - lse;
            la[l + 32][cc] = v1 - lse;
        }
        __syncthreads();
    }
    for (int idx = tid; idx < 4096; idx += 1024) {
        int i = idx >> 6, j = idx & 63;
        la[i][j] = __expf(la[i][j]);
    }
    __syncthreads();
    float local = 0.f;
    for (int idx = tid; idx < 8192; idx += 1024) {
        int i = idx >> 7, d = idx & 127;
        const float* ce = &g_em[(b * 128 + 64) * cD + d];
        float pc = 0.f;
#pragma unroll
        for (int j = 0; j < 64; j++) pc = fmaf(la[i][j], ce[j * cD], pc);
        float qv = g_em[(b * 128 + i) * cD + d];
        local += fmaxf(qv - pc, 0.f);
    }
    local = warp_sum(local);
    if (l == 0) red[w] = local;
    __syncthreads();
    if (tid == 0) {
        float tot = 0.f;
        for (int i = 0; i < 32; i++) tot += red[i];
        out[b] += -0.9f * tot;
    }
}

// ---------------- launch ----------------
extern "C" void kernel_launch(void* const* d_in, const int* in_sizes, int n_in,
                              void* d_out, int out_size) {
    const float* nf      = (const float*)d_in[0];
    const float* ef      = (const float*)d_in[1];
    const float* enc_nw  = (const float*)d_in[2];
    const float* enc_nb  = (const float*)d_in[3];
    const float* enc_ew  = (const float*)d_in[4];
    const float* enc_eb  = (const float*)d_in[5];
    const float* msg_w1  = (const float*)d_in[6];
    const float* msg_b1  = (const float*)d_in[7];
    const float* msg_w2  = (const float*)d_in[8];
    const float* msg_b2  = (const float*)d_in[9];
    const float* rmsg_w1 = (const float*)d_in[10];
    const float* rmsg_b1 = (const float*)d_in[11];
    const float* rmsg_w2 = (const float*)d_in[12];
    const float* rmsg_b2 = (const float*)d_in[13];
    const float* upd_w1  = (const float*)d_in[14];
    const float* upd_b1  = (const float*)d_in[15];
    const float* upd_w2  = (const float*)d_in[16];
    const float* upd_b2  = (const float*)d_in[17];
    const float* sk_w1   = (const float*)d_in[18];
    const float* sk_b1   = (const float*)d_in[19];
    const float* sk_w2   = (const float*)d_in[20];
    const float* sk_b2   = (const float*)d_in[21];
    const int* from_idx  = (const int*)d_in[22];
    const int* to_idx    = (const int*)d_in[23];
    const int* qs        = (const int*)d_in[24];
    const int* cs        = (const int*)d_in[25];
    float* out = (float*)d_out;

    unsigned char *wt = nullptr, *d_hsp = nullptr, *d_esp = nullptr;
    float *d_gh = nullptr, *d_ge = nullptr, *d_gpre = nullptr, *d_gepre = nullptr, *d_gagg = nullptr;
    cudaGetSymbolAddress((void**)&wt, g_wt);
    cudaGetSymbolAddress((void**)&d_gh, g_h);
    cudaGetSymbolAddress((void**)&d_ge, g_e);
    cudaGetSymbolAddress((void**)&d_gpre, g_pre);
    cudaGetSymbolAddress((void**)&d_gepre, g_epre);
    cudaGetSymbolAddress((void**)&d_gagg, g_agg);
    cudaGetSymbolAddress((void**)&d_hsp, g_hsp);
    cudaGetSymbolAddress((void**)&d_esp, g_esp);

    cudaFuncSetAttribute(pre_gemm, cudaFuncAttributeMaxDynamicSharedMemorySize, SMEM_PRE);
    cudaFuncSetAttribute(edge2<0>, cudaFuncAttributeMaxDynamicSharedMemorySize, SMEM_EDGE2);
    cudaFuncSetAttribute(edge2<1>, cudaFuncAttributeMaxDynamicSharedMemorySize, SMEM_EDGE2);
    cudaFuncSetAttribute(upd_mlp,  cudaFuncAttributeMaxDynamicSharedMemorySize, SMEM_UPD);

    // weight prep
    prep_all<<<1408, 256>>>(msg_w1, rmsg_w1, upd_w1, msg_w2, rmsg_w2, upd_w2, wt);

    // encode
    encode16<<<cN / 16, 128>>>(nf, enc_nw, enc_nb, 0);
    encode16<<<cE / 16, 128>>>(ef, enc_ew, enc_eb, 1);

    // one-time: split e, edge precompute g_epre = e @ [W1c|R1c] + [b1m|b1r]
    split_rows<<<(cE * 64) / 256, 256>>>(d_ge, d_esp, d_esp + (size_t)cE * 256, cE);
    pre_gemm<<<dim3(cE / 32, 4), 256, SMEM_PRE>>>(d_esp, d_esp + (size_t)cE * 256,
                                                  wt + OFF_WEC, 1024, 131072,
                                                  d_gepre, 512, msg_b1, rmsg_b1);

    // 3 message-passing steps
    for (int step = 0; step < 3; step++) {
        cudaMemsetAsync(d_gagg, 0, (size_t)cN * cD * sizeof(float));
        split_rows<<<(cN * 64) / 256, 256>>>(d_gh, d_hsp, d_hsp + (size_t)cN * 256, cN);
        pre_gemm<<<dim3(cN / 32, 8), 256, SMEM_PRE>>>(d_hsp, d_hsp + (size_t)cN * 256,
                                                      wt + OFF_WCAT, 2048, 262144,
                                                      d_gpre, 1024, nullptr, nullptr);
        edge2<0><<<cE / 32, 256, SMEM_EDGE2>>>(from_idx, to_idx, wt, msg_b2, rmsg_b2);
        upd_mlp<<<cN / 32, 256, SMEM_UPD>>>(wt, upd_b1, upd_b2);
    }

    // final messages -> em = f + r
    split_rows<<<(cN * 64) / 256, 256>>>(d_gh, d_hsp, d_hsp + (size_t)cN * 256, cN);
    pre_gemm<<<dim3(cN / 32, 8), 256, SMEM_PRE>>>(d_hsp, d_hsp + (size_t)cN * 256,
                                                  wt + OFF_WCAT, 2048, 262144,
                                                  d_gpre, 1024, nullptr, nullptr);
    edge2<1><<<cE / 32, 256, SMEM_EDGE2>>>(from_idx, to_idx, wt, msg_b2, rmsg_b2);

    // tail
    sk_kernel<<<cB * 2 * cMAXN / 4, 256>>>(sk_w1, sk_b1, sk_w2, sk_b2, qs, cs);
    node_plan_kernel<<<cB, 1024>>>();
    node_align_kernel<<<cB, 256>>>(out);
    edge_align_kernel<<<cB, 1024>>>(from_idx, to_idx, out);
}

// round 14
// speedup vs baseline: 1.0224x; 1.0224x over previous
#include <cuda_runtime.h>
#include <cuda_bf16.h>
#include <cstdint>

// ---------------- problem constants ----------------
constexpr int cB    = 256;
constexpr int cNPG  = 28;
constexpr int cMAXN = 32;
constexpr int cD    = 128;
constexpr int cN    = 2 * cB * cNPG;   // 14336 nodes
constexpr int cE    = 2 * cB * 64;     // 32768 edges

// ---------------- scratch (device globals) ----------------
__device__ float g_h[cN * cD];
__device__ float g_e[cE * cD];
__device__ float g_agg[cN * cD];
__device__ float g_em[cE * cD];
__device__ float g_tqc[cB * 2 * cMAXN * 64];
__device__ float g_plan[cB * cMAXN * cMAXN];
__device__ float g_pre[cN * 1024];     // [h@W1a | h@W1b | h@R1a | h@R1b]
__device__ float g_epre[cE * 512];     // [e@W1c + b1m | e@R1c + b1r]
// bf16 hi/lo pre-split inputs (swizzled 256B rows): hi block then lo block
__device__ __align__(256) unsigned char g_hsp[cN * 512];
__device__ __align__(256) unsigned char g_esp[cE * 512];

// weight scratch (bf16 hi then lo per matrix)
__device__ __align__(256) unsigned char g_wt[1441792];
constexpr size_t OFF_UPD1  = 0;        // 256x256 : 262144 B
constexpr size_t OFF_MSG2  = 262144;   // 256x128 : 131072 B
constexpr size_t OFF_RMSG2 = 393216;
constexpr size_t OFF_UPD2  = 524288;
constexpr size_t OFF_WCAT  = 655360;   // 128x1024: 524288 B
constexpr size_t OFF_WEC   = 1179648;  // 128x512 : 262144 B

// ---------------- smem layouts ----------------
// pre_gemm: X hi 8K | X lo 8K | W bufs 2x32K
constexpr int SMEM_PRE = 81920;
// edge2: H hi 16K | H lo 16K | W2 bufs 2x16K | idx
constexpr int e2W2B = 32768;
constexpr int e2IDX = 65536;
constexpr int SMEM_EDGE2 = 65792;
// upd
constexpr int uX_HI = 0;
constexpr int uX_LO = 16384;
constexpr int uWB   = 32768;
constexpr int uW2B  = 65536;
constexpr int SMEM_UPD = 98304;

// ---------------- PTX helpers (portable) ----------------
__device__ __forceinline__ uint32_t smem_u32(const void* p) {
    uint32_t a;
    asm("{ .reg .u64 t; cvta.to.shared.u64 t, %1; cvt.u32.u64 %0, t; }" : "=r"(a) : "l"(p));
    return a;
}
__device__ __forceinline__ void ldsm_x4(uint32_t* r, uint32_t addr) {
    asm volatile("ldmatrix.sync.aligned.m8n8.x4.shared.b16 {%0,%1,%2,%3}, [%4];"
        : "=r"(r[0]), "=r"(r[1]), "=r"(r[2]), "=r"(r[3]) : "r"(addr));
}
__device__ __forceinline__ void ldsm_x4t(uint32_t* r, uint32_t addr) {
    asm volatile("ldmatrix.sync.aligned.m8n8.x4.trans.shared.b16 {%0,%1,%2,%3}, [%4];"
        : "=r"(r[0]), "=r"(r[1]), "=r"(r[2]), "=r"(r[3]) : "r"(addr));
}
__device__ __forceinline__ void mma16816(float* d, const uint32_t* a, const uint32_t* b) {
    asm volatile(
        "mma.sync.aligned.m16n8k16.row.col.f32.bf16.bf16.f32 "
        "{%0,%1,%2,%3}, {%4,%5,%6,%7}, {%8,%9}, {%0,%1,%2,%3};"
        : "+f"(d[0]), "+f"(d[1]), "+f"(d[2]), "+f"(d[3])
        : "r"(a[0]), "r"(a[1]), "r"(a[2]), "r"(a[3]), "r"(b[0]), "r"(b[1]));
}
__device__ __forceinline__ void cp16(uint32_t dst, const void* src) {
    asm volatile("cp.async.cg.shared.global [%0], [%1], 16;" :: "r"(dst), "l"(src));
}
#define CP_COMMIT() asm volatile("cp.async.commit_group;" ::: "memory")
#define CP_WAIT0()  asm volatile("cp.async.wait_group 0;" ::: "memory")

__device__ __forceinline__ uint32_t bf16_split2(float x0, float x1, uint32_t& lo_out) {
    __nv_bfloat16 h0 = __float2bfloat16(x0);
    __nv_bfloat16 h1 = __float2bfloat16(x1);
    __nv_bfloat16 l0 = __float2bfloat16(x0 - __bfloat162float(h0));
    __nv_bfloat16 l1 = __float2bfloat16(x1 - __bfloat162float(h1));
    lo_out = (uint32_t)__bfloat16_as_ushort(l0) | ((uint32_t)__bfloat16_as_ushort(l1) << 16);
    return (uint32_t)__bfloat16_as_ushort(h0) | ((uint32_t)__bfloat16_as_ushort(h1) << 16);
}

__device__ __forceinline__ float warp_max(float v) {
#pragma unroll
    for (int o = 16; o > 0; o >>= 1) v = fmaxf(v, __shfl_xor_sync(0xffffffffu, v, o));
    return v;
}
__device__ __forceinline__ float warp_sum(float v) {
#pragma unroll
    for (int o = 16; o > 0; o >>= 1) v += __shfl_xor_sync(0xffffffffu, v, o);
    return v;
}

// ---------------- fused weight prep ----------------
__global__ void prep_all(const float* __restrict__ m1, const float* __restrict__ r1w,
                         const float* __restrict__ u1, const float* __restrict__ m2,
                         const float* __restrict__ r2w, const float* __restrict__ u2,
                         unsigned char* __restrict__ wt) {
    int idx = blockIdx.x * 256 + threadIdx.x;
    if (idx >= 360448) return;
    float x; unsigned short* d; int l, losz;
    if (idx < 65536) {
        l = idx; x = u1[l]; d = (unsigned short*)(wt + OFF_UPD1); losz = 65536;
    } else if (idx < 98304) {
        l = idx - 65536; x = m2[l]; d = (unsigned short*)(wt + OFF_MSG2); losz = 32768;
    } else if (idx < 131072) {
        l = idx - 98304; x = r2w[l]; d = (unsigned short*)(wt + OFF_RMSG2); losz = 32768;
    } else if (idx < 163840) {
        l = idx - 131072; x = u2[l]; d = (unsigned short*)(wt + OFF_UPD2); losz = 32768;
    } else if (idx < 294912) {
        l = idx - 163840;
        int k = l >> 10, n = l & 1023;
        if (n < 256)      x = m1[k * 256 + n];
        else if (n < 512) x = m1[(128 + k) * 256 + (n - 256)];
        else if (n < 768) x = r1w[k * 256 + (n - 512)];
        else              x = r1w[(128 + k) * 256 + (n - 768)];
        d = (unsigned short*)(wt + OFF_WCAT); losz = 131072;
    } else {
        l = idx - 294912;
        int k = l >> 9, n = l & 511;
        x = (n < 256) ? m1[(256 + k) * 256 + n] : r1w[(256 + k) * 256 + (n - 256)];
        d = (unsigned short*)(wt + OFF_WEC); losz = 65536;
    }
    __nv_bfloat16 hb = __float2bfloat16(x);
    __nv_bfloat16 lb = __float2bfloat16(x - __bfloat162float(hb));
    d[l]        = __bfloat16_as_ushort(hb);
    d[losz + l] = __bfloat16_as_ushort(lb);
}

// ---------------- split fp32 [R][128] -> swizzled bf16 hi/lo 256B rows ----------------
__global__ void __launch_bounds__(256) split_rows(const float* __restrict__ src,
                                                  unsigned char* __restrict__ hi,
                                                  unsigned char* __restrict__ lo, int nrows) {
    int idx = blockIdx.x * 256 + threadIdx.x;
    if (idx >= nrows * 64) return;
    int r = idx >> 6, j = idx & 63;
    float2 v = *(const float2*)&src[(size_t)r * 128 + 2 * j];
    uint32_t l, h = bf16_split2(v.x, v.y, l);
    uint32_t o = (uint32_t)r * 256 + (((uint32_t)(4 * j)) ^ ((uint32_t)(r & 7) << 4));
    *(uint32_t*)(hi + o) = h;
    *(uint32_t*)(lo + o) = l;
}

// ---------------- encoder ----------------
__global__ void __launch_bounds__(128) encode16(const float* __restrict__ x,
                                                const float* __restrict__ W,
                                                const float* __restrict__ bias, int which) {
    __shared__ float sW[32 * 128];
    __shared__ float sx[16][32];
    int tid = threadIdx.x;
    int r0 = blockIdx.x * 16;
    for (int i = tid; i < 4096; i += 128) sW[i] = W[i];
    for (int i = tid; i < 512; i += 128) sx[i >> 5][i & 31] = x[r0 * 32 + i];
    __syncthreads();
    float b = bias[tid];
    float* dst = (which == 0) ? g_h : g_e;
#pragma unroll 4
    for (int rr = 0; rr < 16; rr++) {
        float acc = b;
#pragma unroll
        for (int k = 0; k < 32; k++) acc = fmaf(sx[rr][k], sW[k * 128 + tid], acc);
        dst[(size_t)(r0 + rr) * 128 + tid] = acc;
    }
}

// ---------------- pre_gemm: [32 x 128] @ [128 x 256-slice] -> fp32 ----------------
// X from pre-split bf16 global (swizzled 256B rows). Slice col base = blockIdx.y*256.
__global__ void __launch_bounds__(256, 2) pre_gemm(
    const unsigned char* __restrict__ xhi, const unsigned char* __restrict__ xlo,
    const unsigned char* __restrict__ w, int wRowB, int wLoOff,
    float* __restrict__ dst, int dstStride,
    const float* __restrict__ biasA, const float* __restrict__ biasB) {
    extern __shared__ __align__(16) unsigned char smem[];
    const uint32_t sb = smem_u32(smem);
    const int tid = threadIdx.x, lane = tid & 31, wid = tid >> 5;
    const int r0 = blockIdx.x * 32;
    const int cbk = blockIdx.y;
    const float* bias = (cbk == 0) ? biasA : biasB;

    // X copy (hi 8K + lo 8K) — swizzle preserved byte-for-byte ((r0+r)&7 == r&7)
    for (int i = tid; i < 1024; i += 256) {
        int comp = i >> 9, t = i & 511;
        int r = t >> 4, cc = t & 15;
        cp16(sb + comp * 8192 + r * 256 + cc * 16,
             (comp ? xlo : xhi) + (size_t)(r0 + r) * 256 + cc * 16);
    }
    // W chunk 0 (32 k-rows x 256 cols, hi+lo)
    for (int i = tid; i < 2048; i += 256) {
        int comp = i >> 10, rr = (i >> 5) & 31, cc = i & 31;
        cp16(sb + 16384 + comp * 16384 + rr * 512 + ((cc * 16) ^ ((rr & 7) << 4)),
             w + (size_t)comp * wLoOff + (size_t)rr * wRowB + cbk * 512 + cc * 16);
    }
    CP_COMMIT();

    const int rg = (wid & 1) << 4;
    const int n0 = (wid >> 1) << 6;
    const int m_ = lane >> 3, r_ = lane & 7;
    const int arow = rg + ((m_ & 1) << 3) + r_;
    const int acol = (m_ >> 1) << 3;
    const int bRow = lane & 15, bAdd = (lane >> 4) << 3;
    const uint32_t aswz = (uint32_t)(arow & 7) << 4;
    const uint32_t bswz = (uint32_t)(bRow & 7) << 4;
    const uint32_t aHiB = sb + (uint32_t)arow * 256;
    const uint32_t aLoB = aHiB + 8192;

    float acc[8][4];
#pragma unroll
    for (int j = 0; j < 8; j++)
#pragma unroll
        for (int q = 0; q < 4; q++) acc[j][q] = 0.f;

    for (int c = 0; c < 4; c++) {
        CP_WAIT0();
        __syncthreads();
        if (c + 1 < 4) {
            const int nb = (c + 1) & 1;
            for (int i = tid; i < 2048; i += 256) {
                int comp = i >> 10, rr = (i >> 5) & 31, cc = i & 31;
                cp16(sb + 16384 + nb * 32768 + comp * 16384 + rr * 512 + ((cc * 16) ^ ((rr & 7) << 4)),
                     w + (size_t)comp * wLoOff + (size_t)((c + 1) * 32 + rr) * wRowB + cbk * 512 + cc * 16);
            }
            CP_COMMIT();
        }
        const uint32_t wb = sb + 16384 + (c & 1) * 32768;
#pragma unroll
        for (int kt = 0; kt < 2; kt++) {
            int kg = c * 32 + kt * 16;
            uint32_t aHi[4], aLo[4];
            uint32_t ac = ((uint32_t)((acol + kg) * 2)) ^ aswz;
            ldsm_x4(aHi, aHiB + ac);
            ldsm_x4(aLo, aLoB + ac);
            uint32_t bb = wb + (uint32_t)(kt * 16 + bRow) * 512;
#pragma unroll
            for (int j = 0; j < 4; j++) {
                uint32_t cbyte = ((uint32_t)((n0 + bAdd + j * 16) * 2)) ^ bswz;
                uint32_t bh[4], bl[4];
                ldsm_x4t(bh, bb + cbyte);
                ldsm_x4t(bl, bb + 16384 + cbyte);
                mma16816(acc[2 * j],     aHi, bh);
                mma16816(acc[2 * j + 1], aHi, bh + 2);
                mma16816(acc[2 * j],     aHi, bl);
                mma16816(acc[2 * j + 1], aHi, bl + 2);
                mma16816(acc[2 * j],     aLo, bh);
                mma16816(acc[2 * j + 1], aLo, bh + 2);
            }
        }
    }
    // epilogue
    const int cb_ = n0 + (lane & 3) * 2;
    const int r1 = rg + (lane >> 2);
#pragma unroll
    for (int j = 0; j < 8; j++) {
        int cc = cb_ + j * 8;
        float b0 = bias ? __ldg(bias + cc) : 0.f;
        float b1v = bias ? __ldg(bias + cc + 1) : 0.f;
        size_t o0 = (size_t)(r0 + r1) * dstStride + cbk * 256 + cc;
        size_t o1 = (size_t)(r0 + r1 + 8) * dstStride + cbk * 256 + cc;
        dst[o0]     = acc[j][0] + b0;
        dst[o0 + 1] = acc[j][1] + b1v;
        dst[o1]     = acc[j][2] + b0;
        dst[o1 + 1] = acc[j][3] + b1v;
    }
}

// ---------------- edge2: gather-add-relu + stage2 GEMM, msg then rmsg ----------------
template <int MODE>
__global__ void __launch_bounds__(256, 3) edge2(
    const int* __restrict__ from_idx, const int* __restrict__ to_idx,
    const unsigned char* __restrict__ wt,
    const float* __restrict__ b2m, const float* __restrict__ b2r) {
    extern __shared__ __align__(16) unsigned char smem[];
    const uint32_t sb = smem_u32(smem);
    const int tid = threadIdx.x, lane = tid & 31, wid = tid >> 5;
    const int e0 = blockIdx.x * 32;
    int* sF = (int*)(smem + e2IDX);
    int* sT = sF + 32;
    if (tid < 32) { sF[tid] = from_idx[e0 + tid]; sT[tid] = to_idx[e0 + tid]; }
    __syncthreads();

    const int rg = (wid & 1) << 4;
    const int n2 = (wid >> 1) << 5;
    const int m_ = lane >> 3, r_ = lane & 7;
    const int arow = rg + ((m_ & 1) << 3) + r_;
    const int acol = (m_ >> 1) << 3;
    const int bRow = lane & 15, bAdd = (lane >> 4) << 3;
    const uint32_t aswz = (uint32_t)(arow & 7) << 4;
    const uint32_t bswz = (uint32_t)(bRow & 7) << 4;
    const uint32_t aHiB = sb + (uint32_t)arow * 512;
    const uint32_t aLoB = aHiB + 16384;

#pragma unroll
    for (int ph = 0; ph < 2; ph++) {
        const unsigned char* w2t = wt + (ph ? OFF_RMSG2 : OFF_MSG2);
        const float* b2 = ph ? b2r : b2m;
        if (ph) __syncthreads();
        for (int i = tid; i < 1024; i += 256) {
            int comp = i >> 9, rr = (i >> 4) & 31, cc = i & 15;
            cp16(sb + e2W2B + comp * 8192 + rr * 256 + ((cc * 16) ^ ((rr & 7) << 4)),
                 w2t + (size_t)comp * 65536 + (size_t)rr * 256 + cc * 16);
        }
        CP_COMMIT();
        for (int i = tid; i < 2048; i += 256) {
            int r = i >> 6, c4 = (i & 63) << 2;
            int ia = ph ? sT[r] : sF[r];
            int ib = ph ? sF[r] : sT[r];
            const float4 fa = *(const float4*)&g_pre[(size_t)ia * 1024 + ph * 512 + c4];
            const float4 fb = *(const float4*)&g_pre[(size_t)ib * 1024 + ph * 512 + 256 + c4];
            const float4 fe = *(const float4*)&g_epre[(size_t)(e0 + r) * 512 + ph * 256 + c4];
            float v0 = fmaxf(fa.x + fb.x + fe.x, 0.f);
            float v1 = fmaxf(fa.y + fb.y + fe.y, 0.f);
            float v2 = fmaxf(fa.z + fb.z + fe.z, 0.f);
            float v3 = fmaxf(fa.w + fb.w + fe.w, 0.f);
            uint32_t lo0, hi0 = bf16_split2(v0, v1, lo0);
            uint32_t lo1, hi1 = bf16_split2(v2, v3, lo1);
            uint32_t o = (uint32_t)r * 512 + (((uint32_t)(c4 * 2)) ^ ((uint32_t)(r & 7) << 4));
            *(uint32_t*)(smem + o)             = hi0;
            *(uint32_t*)(smem + o + 4)         = hi1;
            *(uint32_t*)(smem + 16384 + o)     = lo0;
            *(uint32_t*)(smem + 16384 + o + 4) = lo1;
        }
        float acc2[4][4];
#pragma unroll
        for (int j = 0; j < 4; j++)
#pragma unroll
            for (int q = 0; q < 4; q++) acc2[j][q] = 0.f;
        for (int c = 0; c < 8; c++) {
            CP_WAIT0();
            __syncthreads();
            if (c + 1 < 8) {
                const int nb = (c + 1) & 1;
                for (int i = tid; i < 1024; i += 256) {
                    int comp = i >> 9, rr = (i >> 4) & 31, cc = i & 15;
                    cp16(sb + e2W2B + nb * 16384 + comp * 8192 + rr * 256 + ((cc * 16) ^ ((rr & 7) << 4)),
                         w2t + (size_t)comp * 65536 + (size_t)((c + 1) * 32 + rr) * 256 + cc * 16);
                }
                CP_COMMIT();
            }
            const uint32_t wb2 = sb + e2W2B + (c & 1) * 16384;
#pragma unroll
            for (int kt = 0; kt < 2; kt++) {
                int kg = c * 32 + kt * 16;
                uint32_t aHi[4], aLo[4];
                uint32_t ac = ((uint32_t)((acol + kg) * 2)) ^ aswz;
                ldsm_x4(aHi, aHiB + ac);
                ldsm_x4(aLo, aLoB + ac);
                uint32_t bb = wb2 + (uint32_t)(kt * 16 + bRow) * 256;
#pragma unroll
                for (int j = 0; j < 2; j++) {
                    uint32_t cbyte = ((uint32_t)((n2 + bAdd + j * 16) * 2)) ^ bswz;
                    uint32_t bh[4], bl[4];
                    ldsm_x4t(bh, bb + cbyte);
                    ldsm_x4t(bl, bb + 8192 + cbyte);
                    mma16816(acc2[2 * j],     aHi, bh);
                    mma16816(acc2[2 * j + 1], aHi, bh + 2);
                    mma16816(acc2[2 * j],     aHi, bl);
                    mma16816(acc2[2 * j + 1], aHi, bl + 2);
                    mma16816(acc2[2 * j],     aLo, bh);
                    mma16816(acc2[2 * j + 1], aLo, bh + 2);
                }
            }
        }
        const int cb_ = n2 + (lane & 3) * 2;
        const int r1 = rg + (lane >> 2);
#pragma unroll
        for (int j = 0; j < 4; j++) {
            int cc = cb_ + j * 8;
            float b0 = __ldg(b2 + cc), b1v = __ldg(b2 + cc + 1);
            float v00 = acc2[j][0] + b0, v01 = acc2[j][1] + b1v;
            float v10 = acc2[j][2] + b0, v11 = acc2[j][3] + b1v;
            if (MODE == 0) {
                int nA = ph ? sF[r1] : sT[r1];
                int nB = ph ? sF[r1 + 8] : sT[r1 + 8];
                atomicAdd(&g_agg[(size_t)nA * cD + cc],     v00);
                atomicAdd(&g_agg[(size_t)nA * cD + cc + 1], v01);
                atomicAdd(&g_agg[(size_t)nB * cD + cc],     v10);
                atomicAdd(&g_agg[(size_t)nB * cD + cc + 1], v11);
            } else {
                float* d0 = &g_em[(size_t)(e0 + r1) * cD + cc];
                float* d1 = &g_em[(size_t)(e0 + r1 + 8) * cD + cc];
                if (ph == 0) {
                    d0[0] = v00; d0[1] = v01;
                    d1[0] = v10; d1[1] = v11;
                } else {
                    d0[0] += v00; d0[1] += v01;
                    d1[0] += v10; d1[1] += v11;
                }
            }
        }
    }
}

// ---------------- run_mlp (used by upd only) ----------------
template <int K1, int XST, int XHI, int XLO, int WB, int W2B>
__device__ __forceinline__ void run_mlp(
    unsigned char* smem, uint32_t sb,
    const unsigned char* __restrict__ w1t, const float* __restrict__ b1p,
    const unsigned char* __restrict__ w2t,
    int tid, int lane, int wid, float out[4][4]) {
    const int rg = (wid & 1) << 4;
    const int n0 = (wid >> 1) << 6;
    const int n2 = (wid >> 1) << 5;
    const int m_ = lane >> 3, r_ = lane & 7;
    const int arow = rg + ((m_ & 1) << 3) + r_;
    const int acol = (m_ >> 1) << 3;
    const int bRow = lane & 15;
    const int bAdd = (lane >> 4) << 3;
    const uint32_t aswz = (uint32_t)(arow & 7) << 4;
    const uint32_t aHiB = sb + XHI + (uint32_t)arow * XST;
    const uint32_t aLoB = sb + XLO + (uint32_t)arow * XST;
    const uint32_t bswz = (uint32_t)(bRow & 7) << 4;

    float acc[8][4];
#pragma unroll
    for (int j = 0; j < 8; j++)
#pragma unroll
        for (int q = 0; q < 4; q++) acc[j][q] = 0.f;

    constexpr int NC1 = K1 / 32;
    for (int i = tid; i < 2048; i += 256) {
        int comp = i >> 10, rr = (i >> 5) & 31, cc = i & 31;
        cp16(sb + WB + comp * 16384 + rr * 512 + ((cc * 16) ^ ((rr & 7) << 4)),
             w1t + (size_t)comp * (K1 * 512) + (size_t)rr * 512 + cc * 16);
    }
    CP_COMMIT();

    for (int c = 0; c < NC1; c++) {
        CP_WAIT0();
        __syncthreads();
        if (c + 1 < NC1) {
            const int nb = (c + 1) & 1;
            for (int i = tid; i < 2048; i += 256) {
                int comp = i >> 10, rr = (i >> 5) & 31, cc = i & 31;
                cp16(sb + WB + nb * 32768 + comp * 16384 + rr * 512 + ((cc * 16) ^ ((rr & 7) << 4)),
                     w1t + (size_t)comp * (K1 * 512) + (size_t)((c + 1) * 32 + rr) * 512 + cc * 16);
            }
            CP_COMMIT();
        }
        const uint32_t wb1 = sb + WB + (c & 1) * 32768;
#pragma unroll
        for (int kt = 0; kt < 2; kt++) {
            int kg = c * 32 + kt * 16;
            uint32_t aHi[4], aLo[4];
            uint32_t ac = ((uint32_t)((acol + kg) * 2)) ^ aswz;
            ldsm_x4(aHi, aHiB + ac);
            ldsm_x4(aLo, aLoB + ac);
            uint32_t bb = wb1 + (uint32_t)(kt * 16 + bRow) * 512;
#pragma unroll
            for (int j = 0; j < 4; j++) {
                uint32_t cbyte = ((uint32_t)((n0 + bAdd + j * 16) * 2)) ^ bswz;
                uint32_t bh[4], bl[4];
                ldsm_x4t(bh, bb + cbyte);
                ldsm_x4t(bl, bb + 16384 + cbyte);
                mma16816(acc[2 * j],     aHi, bh);
                mma16816(acc[2 * j + 1], aHi, bh + 2);
                mma16816(acc[2 * j],     aHi, bl);
                mma16816(acc[2 * j + 1], aHi, bl + 2);
                mma16816(acc[2 * j],     aLo, bh);
                mma16816(acc[2 * j + 1], aLo, bh + 2);
            }
        }
    }
    __syncthreads();

    {
        int cb = n0 + (lane & 3) * 2;
        int r1 = rg + (lane >> 2);
        uint32_t s1 = (uint32_t)(r1 & 7) << 4;
#pragma unroll
        for (int j = 0; j < 8; j++) {
            int cc = cb + j * 8;
            float b0 = __ldg(b1p + cc), b1v = __ldg(b1p + cc + 1);
            float v00 = fmaxf(acc[j][0] + b0, 0.f), v01 = fmaxf(acc[j][1] + b1v, 0.f);
            float v10 = fmaxf(acc[j][2] + b0, 0.f), v11 = fmaxf(acc[j][3] + b1v, 0.f);
            uint32_t lo0, hi0 = bf16_split2(v00, v01, lo0);
            uint32_t lo1, hi1 = bf16_split2(v10, v11, lo1);
            uint32_t o1 = ((uint32_t)(cc * 2)) ^ s1;
            *(uint32_t*)(smem + WB + r1 * 512 + o1)               = hi0;
            *(uint32_t*)(smem + WB + 16384 + r1 * 512 + o1)       = lo0;
            *(uint32_t*)(smem + WB + (r1 + 8) * 512 + o1)         = hi1;
            *(uint32_t*)(smem + WB + 16384 + (r1 + 8) * 512 + o1) = lo1;
        }
    }

    float acc2[4][4];
#pragma unroll
    for (int j = 0; j < 4; j++)
#pragma unroll
        for (int q = 0; q < 4; q++) acc2[j][q] = 0.f;
    const uint32_t a2HiB = sb + WB + (uint32_t)arow * 512;
    const uint32_t a2LoB = a2HiB + 16384;

    for (int i = tid; i < 1024; i += 256) {
        int comp = i >> 9, rr = (i >> 4) & 31, cc = i & 15;
        cp16(sb + W2B + comp * 8192 + rr * 256 + ((cc * 16) ^ ((rr & 7) << 4)),
             w2t + (size_t)comp * 65536 + (size_t)rr * 256 + cc * 16);
    }
    CP_COMMIT();

    for (int c = 0; c < 8; c++) {
        CP_WAIT0();
        __syncthreads();
        if (c + 1 < 8) {
            const int nb = (c + 1) & 1;
            for (int i = tid; i < 1024; i += 256) {
                int comp = i >> 9, rr = (i >> 4) & 31, cc = i & 15;
                cp16(sb + W2B + nb * 16384 + comp * 8192 + rr * 256 + ((cc * 16) ^ ((rr & 7) << 4)),
                     w2t + (size_t)comp * 65536 + (size_t)((c + 1) * 32 + rr) * 256 + cc * 16);
            }
            CP_COMMIT();
        }
        const uint32_t wb2 = sb + W2B + (c & 1) * 16384;
#pragma unroll
        for (int kt = 0; kt < 2; kt++) {
            int kg = c * 32 + kt * 16;
            uint32_t aHi[4], aLo[4];
            uint32_t ac = ((uint32_t)((acol + kg) * 2)) ^ aswz;
            ldsm_x4(aHi, a2HiB + ac);
            ldsm_x4(aLo, a2LoB + ac);
            uint32_t bb = wb2 + (uint32_t)(kt * 16 + bRow) * 256;
#pragma unroll
            for (int j = 0; j < 2; j++) {
                uint32_t cbyte = ((uint32_t)((n2 + bAdd + j * 16) * 2)) ^ bswz;
                uint32_t bh[4], bl[4];
                ldsm_x4t(bh, bb + cbyte);
                ldsm_x4t(bl, bb + 8192 + cbyte);
                mma16816(acc2[2 * j],     aHi, bh);
                mma16816(acc2[2 * j + 1], aHi, bh + 2);
                mma16816(acc2[2 * j],     aHi, bl);
                mma16816(acc2[2 * j + 1], aHi, bl + 2);
                mma16816(acc2[2 * j],     aLo, bh);
                mma16816(acc2[2 * j + 1], aLo, bh + 2);
            }
        }
    }
    __syncthreads();
#pragma unroll
    for (int j = 0; j < 4; j++)
#pragma unroll
        for (int q = 0; q < 4; q++) out[j][q] = acc2[j][q];
}

// ---------------- upd kernel: h += mlp([agg, h]) ----------------
__global__ void __launch_bounds__(256, 2) upd_mlp(
    const unsigned char* __restrict__ wt,
    const float* __restrict__ b1p, const float* __restrict__ b2p) {
    extern __shared__ __align__(16) unsigned char smem[];
    const uint32_t sb = smem_u32(smem);
    const int tid = threadIdx.x, lane = tid & 31, wid = tid >> 5;
    const int e0 = blockIdx.x * 32;

    for (int i = tid; i < 2048; i += 256) {
        int r = i >> 6, q = i & 63;
        int seg = q >> 5, c4 = (q & 31) << 2;
        const float* src = (seg == 0 ? g_agg : g_h) + (size_t)(e0 + r) * cD + c4;
        float4 v = *(const float4*)src;
        int col = seg * 128 + c4;
        uint32_t lo0, hi0 = bf16_split2(v.x, v.y, lo0);
        uint32_t lo1, hi1 = bf16_split2(v.z, v.w, lo1);
        uint32_t o = (uint32_t)r * 512 + (((uint32_t)(col * 2)) ^ ((uint32_t)(r & 7) << 4));
        *(uint32_t*)(smem + uX_HI + o)     = hi0;
        *(uint32_t*)(smem + uX_HI + o + 4) = hi1;
        *(uint32_t*)(smem + uX_LO + o)     = lo0;
        *(uint32_t*)(smem + uX_LO + o + 4) = lo1;
    }

    float oacc[4][4];
    run_mlp<256, 512, uX_HI, uX_LO, uWB, uW2B>(smem, sb, wt + OFF_UPD1, b1p,
                                               wt + OFF_UPD2, tid, lane, wid, oacc);

    const int rg = (wid & 1) << 4;
    const int n2 = (wid >> 1) << 5;
    const int cb = n2 + (lane & 3) * 2;
    const int r1 = rg + (lane >> 2);
#pragma unroll
    for (int j = 0; j < 4; j++) {
        int cc = cb + j * 8;
        float b0 = __ldg(b2p + cc), b1v = __ldg(b2p + cc + 1);
        g_h[(size_t)(e0 + r1) * cD + cc]         += oacc[j][0] + b0;
        g_h[(size_t)(e0 + r1) * cD + cc + 1]     += oacc[j][1] + b1v;
        g_h[(size_t)(e0 + r1 + 8) * cD + cc]     += oacc[j][2] + b0;
        g_h[(size_t)(e0 + r1 + 8) * cD + cc + 1] += oacc[j][3] + b1v;
    }
}

// ---------------- SK head ----------------
__global__ void __launch_bounds__(256) sk_kernel(
    const float* __restrict__ w1p, const float* __restrict__ b1p,
    const float* __restrict__ w2p, const float* __restrict__ b2p,
    const int* __restrict__ qs, const int* __restrict__ cs) {
    int t = threadIdx.x;
    int lr = t >> 6, j = t & 63;
    int row = blockIdx.x * 4 + lr;
    int b = row >> 6, sp = row & 63, s = sp >> 5, p = sp & 31;
    __shared__ float sx[4][128];
    __shared__ float sh[4][64];
    {
        bool valid = p < cNPG;
        int node = (b * 2 + s) * cNPG + p;
        sx[lr][j]      = valid ? g_h[node * cD + j]      : 0.f;
        sx[lr][j + 64] = valid ? g_h[node * cD + j + 64] : 0.f;
    }
    __syncthreads();
    float a = b1p[j];
#pragma unroll
    for (int k = 0; k < 128; k++) a = fmaf(sx[lr][k], w1p[k * 64 + j], a);
    sh[lr][j] = fmaxf(a, 0.f);
    __syncthreads();
    float o = b2p[j];
#pragma unroll
    for (int k = 0; k < 64; k++) o = fmaf(sh[lr][k], w2p[k * 64 + j], o);
    int size = (s == 0) ? qs[b] : cs[b];
    if (p >= size) o = 0.f;
    g_tqc[row * 64 + j] = o;
}

// ---------------- node scores + Sinkhorn ----------------
__global__ void __launch_bounds__(1024) node_plan_kernel() {
    int b = blockIdx.x;
    int tid = threadIdx.x;
    __shared__ float smq[32][65];
    __shared__ float smc[32][65];
    __shared__ float la[32 * 33];
    for (int idx = tid; idx < 2048; idx += 1024) {
        int r = idx >> 6, d = idx & 63;
        smq[r][d] = g_tqc[b * 4096 + idx];
        smc[r][d] = g_tqc[b * 4096 + 2048 + idx];
    }
    __syncthreads();
    int q = tid >> 5, c = tid & 31;
    float v = 0.f;
#pragma unroll
    for (int d = 0; d < 64; d++) v = fmaf(smq[q][d], smc[c][d], v);
    v *= 10.f;
    {
        float m = warp_max(v);
        float sum = warp_sum(__expf(v - m));
        v -= m + __logf(sum);
        la[q * 33 + c] = v;
        __syncthreads();
        float u = la[c * 33 + q];
        float s = warp_sum(__expf(u));
        u -= __logf(s);
        la[c * 33 + q] = u;
        __syncthreads();
        v = la[q * 33 + c];
    }
    for (int it = 1; it < 20; it++) {
        float s = warp_sum(__expf(v));
        v -= __logf(s);
        la[q * 33 + c] = v;
        __syncthreads();
        float u = la[c * 33 + q];
        s = warp_sum(__expf(u));
        u -= __logf(s);
        la[c * 33 + q] = u;
        __syncthreads();
        v = la[q * 33 + c];
    }
    g_plan[b * 1024 + q * 32 + c] = __expf(v);
}

// ---------------- node alignment ----------------
__global__ void __launch_bounds__(256) node_align_kernel(float* __restrict__ out) {
    int b = blockIdx.x, tid = threadIdx.x;
    __shared__ float sp_[32 * 32];
    __shared__ float scn[32][128];
    __shared__ float red[8];
    for (int idx = tid; idx < 1024; idx += 256) sp_[idx] = g_plan[b * 1024 + idx];
    for (int idx = tid; idx < 4096; idx += 256) {
        int p = idx >> 7, d = idx & 127;
        scn[p][d] = (p < cNPG) ? g_h[((b * 2 + 1) * cNPG + p) * cD + d] : 0.f;
    }
    __syncthreads();
    float local = 0.f;
    for (int idx = tid; idx < 4096; idx += 256) {
        int q = idx >> 7, d = idx & 127;
        float pc = 0.f;
#pragma unroll
        for (int c = 0; c < 32; c++) pc = fmaf(sp_[q * 32 + c], scn[c][d], pc);
        float qv = (q < cNPG) ? g_h[((b * 2) * cNPG + q) * cD + d] : 0.f;
        local += fmaxf(qv - pc, 0.f);
    }
    local = warp_sum(local);
    if ((tid & 31) == 0) red[tid >> 5] = local;
    __syncthreads();
    if (tid == 0) {
        float tot = 0.f;
        for (int i = 0; i < 8; i++) tot += red[i];
        out[b] = -tot;
    }
}

// ---------------- edge kron + Sinkhorn + alignment ----------------
__global__ void __launch_bounds__(1024) edge_align_kernel(
    const int* __restrict__ from_idx, const int* __restrict__ to_idx,
    float* __restrict__ out) {
    int b = blockIdx.x, tid = threadIdx.x;
    __shared__ float T[32 * 32];
    __shared__ float la[64][65];
    __shared__ int qf[64], qt[64], cf[64], ct[64];
    __shared__ float red[32];

    T[tid & 1023] = g_plan[b * 1024 + (tid & 1023)];
    if (tid < 64) {
        qf[tid] = from_idx[b * 128 + tid] % cNPG;
        qt[tid] = to_idx[b * 128 + tid] % cNPG;
        cf[tid] = from_idx[b * 128 + 64 + tid] % cNPG;
        ct[tid] = to_idx[b * 128 + 64 + tid] % cNPG;
    }
    __syncthreads();
    for (int idx = tid; idx < 4096; idx += 1024) {
        int i = idx >> 6, j = idx & 63;
        float s = T[qf[i] * 32 + cf[j]] * T[qt[i] * 32 + ct[j]]
                + T[qf[i] * 32 + ct[j]] * T[qt[i] * 32 + cf[j]];
        la[i][j] = s * 10.f;
    }
    __syncthreads();
    int w = tid >> 5, l = tid & 31;
    for (int it = 0; it < 20; it++) {
#pragma unroll
        for (int rr_ = 0; rr_ < 2; rr_++) {
            int rr = w + rr_ * 32;
            float v0 = la[rr][l], v1 = la[rr][l + 32];
            float s = warp_sum(__expf(v0) + __expf(v1));
            float lse = __logf(s);
            la[rr][l] = v0 - lse;
            la[rr][l + 32] = v1 - lse;
        }
        __syncthreads();
#pragma unroll
        for (int cc_ = 0; cc_ < 2; cc_++) {
            int cc = w + cc_ * 32;
            float v0 = la[l][cc], v1 = la[l + 32][cc];
            float s = warp_sum(__expf(v0) + __expf(v1));
            float lse = __logf(s);
            la[l][cc] = v0 - lse;
            la[l + 32][cc] = v1 - lse;
        }
        __syncthreads();
    }
    for (int idx = tid; idx < 4096; idx += 1024) {
        int i = idx >> 6, j = idx & 63;
        la[i][j] = __expf(la[i][j]);
    }
    __syncthreads();
    float local = 0.f;
    for (int idx = tid; idx < 8192; idx += 1024) {
        int i = idx >> 7, d = idx & 127;
        const float* ce = &g_em[(b * 128 + 64) * cD + d];
        float pc = 0.f;
#pragma unroll
        for (int j = 0; j < 64; j++) pc = fmaf(la[i][j], ce[j * cD], pc);
        float qv = g_em[(b * 128 + i) * cD + d];
        local += fmaxf(qv - pc, 0.f);
    }
    local = warp_sum(local);
    if (l == 0) red[w] = local;
    __syncthreads();
    if (tid == 0) {
        float tot = 0.f;
        for (int i = 0; i < 32; i++) tot += red[i];
        out[b] += -0.9f * tot;
    }
}

// ---------------- launch ----------------
extern "C" void kernel_launch(void* const* d_in, const int* in_sizes, int n_in,
                              void* d_out, int out_size) {
    const float* nf      = (const float*)d_in[0];
    const float* ef      = (const float*)d_in[1];
    const float* enc_nw  = (const float*)d_in[2];
    const float* enc_nb  = (const float*)d_in[3];
    const float* enc_ew  = (const float*)d_in[4];
    const float* enc_eb  = (const float*)d_in[5];
    const float* msg_w1  = (const float*)d_in[6];
    const float* msg_b1  = (const float*)d_in[7];
    const float* msg_w2  = (const float*)d_in[8];
    const float* msg_b2  = (const float*)d_in[9];
    const float* rmsg_w1 = (const float*)d_in[10];
    const float* rmsg_b1 = (const float*)d_in[11];
    const float* rmsg_w2 = (const float*)d_in[12];
    const float* rmsg_b2 = (const float*)d_in[13];
    const float* upd_w1  = (const float*)d_in[14];
    const float* upd_b1  = (const float*)d_in[15];
    const float* upd_w2  = (const float*)d_in[16];
    const float* upd_b2  = (const float*)d_in[17];
    const float* sk_w1   = (const float*)d_in[18];
    const float* sk_b1   = (const float*)d_in[19];
    const float* sk_w2   = (const float*)d_in[20];
    const float* sk_b2   = (const float*)d_in[21];
    const int* from_idx  = (const int*)d_in[22];
    const int* to_idx    = (const int*)d_in[23];
    const int* qs        = (const int*)d_in[24];
    const int* cs        = (const int*)d_in[25];
    float* out = (float*)d_out;

    unsigned char *wt = nullptr, *d_hsp = nullptr, *d_esp = nullptr;
    float *d_gh = nullptr, *d_ge = nullptr, *d_gpre = nullptr, *d_gepre = nullptr, *d_gagg = nullptr;
    cudaGetSymbolAddress((void**)&wt, g_wt);
    cudaGetSymbolAddress((void**)&d_gh, g_h);
    cudaGetSymbolAddress((void**)&d_ge, g_e);
    cudaGetSymbolAddress((void**)&d_gpre, g_pre);
    cudaGetSymbolAddress((void**)&d_gepre, g_epre);
    cudaGetSymbolAddress((void**)&d_gagg, g_agg);
    cudaGetSymbolAddress((void**)&d_hsp, g_hsp);
    cudaGetSymbolAddress((void**)&d_esp, g_esp);

    cudaFuncSetAttribute(pre_gemm, cudaFuncAttributeMaxDynamicSharedMemorySize, SMEM_PRE);
    cudaFuncSetAttribute(edge2<0>, cudaFuncAttributeMaxDynamicSharedMemorySize, SMEM_EDGE2);
    cudaFuncSetAttribute(edge2<1>, cudaFuncAttributeMaxDynamicSharedMemorySize, SMEM_EDGE2);
    cudaFuncSetAttribute(upd_mlp,  cudaFuncAttributeMaxDynamicSharedMemorySize, SMEM_UPD);

    // weight prep
    prep_all<<<1408, 256>>>(msg_w1, rmsg_w1, upd_w1, msg_w2, rmsg_w2, upd_w2, wt);

    // encode
    encode16<<<cN / 16, 128>>>(nf, enc_nw, enc_nb, 0);
    encode16<<<cE / 16, 128>>>(ef, enc_ew, enc_eb, 1);

    // one-time: split e, edge precompute g_epre = e @ [W1c|R1c] + [b1m|b1r]
    split_rows<<<(cE * 64) / 256, 256>>>(d_ge, d_esp, d_esp + (size_t)cE * 256, cE);
    pre_gemm<<<dim3(cE / 32, 2), 256, SMEM_PRE>>>(d_esp, d_esp + (size_t)cE * 256,
                                                  wt + OFF_WEC, 1024, 131072,
                                                  d_gepre, 512, msg_b1, rmsg_b1);

    // 3 message-passing steps
    for (int step = 0; step < 3; step++) {
        cudaMemsetAsync(d_gagg, 0, (size_t)cN * cD * sizeof(float));
        split_rows<<<(cN * 64) / 256, 256>>>(d_gh, d_hsp, d_hsp + (size_t)cN * 256, cN);
        pre_gemm<<<dim3(cN / 32, 4), 256, SMEM_PRE>>>(d_hsp, d_hsp + (size_t)cN * 256,
                                                      wt + OFF_WCAT, 2048, 262144,
                                                      d_gpre, 1024, nullptr, nullptr);
        edge2<0><<<cE / 32, 256, SMEM_EDGE2>>>(from_idx, to_idx, wt, msg_b2, rmsg_b2);
        upd_mlp<<<cN / 32, 256, SMEM_UPD>>>(wt, upd_b1, upd_b2);
    }

    // final messages -> em = f + r
    split_rows<<<(cN * 64) / 256, 256>>>(d_gh, d_hsp, d_hsp + (size_t)cN * 256, cN);
    pre_gemm<<<dim3(cN / 32, 4), 256, SMEM_PRE>>>(d_hsp, d_hsp + (size_t)cN * 256,
                                                  wt + OFF_WCAT, 2048, 262144,
                                                  d_gpre, 1024, nullptr, nullptr);
    edge2<1><<<cE / 32, 256, SMEM_EDGE2>>>(from_idx, to_idx, wt, msg_b2, rmsg_b2);

    // tail
    sk_kernel<<<cB * 2 * cMAXN / 4, 256>>>(sk_w1, sk_b1, sk_w2, sk_b2, qs, cs);
    node_plan_kernel<<<cB, 1024>>>();
    node_align_kernel<<<cB, 256>>>(out);
    edge_align_kernel<<<cB, 1024>>>(from_idx, to_idx, out);
}

// round 16
// speedup vs baseline: 1.5256x; 1.4921x over previous
#include <cuda_runtime.h>
#include <cuda_bf16.h>
#include <cstdint>

// ---------------- problem constants ----------------
constexpr int cB    = 256;
constexpr int cNPG  = 28;
constexpr int cMAXN = 32;
constexpr int cD    = 128;
constexpr int cN    = 2 * cB * cNPG;   // 14336 nodes
constexpr int cE    = 2 * cB * 64;     // 32768 edges

// ---------------- scratch (device globals) ----------------
__device__ float g_h[cN * cD];
__device__ float g_e[cE * cD];
__device__ float g_agg[cN * cD];
__device__ float g_em[cE * cD];
__device__ float g_tqc[cB * 2 * cMAXN * 64];
__device__ float g_plan[cB * cMAXN * cMAXN];
__device__ float g_pre[cN * 1024];     // [h@W1a | h@W1b | h@R1a | h@R1b]
__device__ float g_epre[cE * 512];     // [e@W1c + b1m | e@R1c + b1r]

// weight scratch (bf16 hi then lo per matrix)
__device__ __align__(256) unsigned char g_wt[1441792];
constexpr size_t OFF_UPD1  = 0;        // 256x256 : 262144 B
constexpr size_t OFF_MSG2  = 262144;   // 256x128 : 131072 B
constexpr size_t OFF_RMSG2 = 393216;
constexpr size_t OFF_UPD2  = 524288;
constexpr size_t OFF_WCAT  = 655360;   // 128x1024: 524288 B
constexpr size_t OFF_WEC   = 1179648;  // 128x512 : 262144 B

// ---------------- smem layouts ----------------
// pre_gemm: X hi 8K | X lo 8K | W bufs 2x32K
constexpr int SMEM_PRE = 81920;
// edge2: H hi 16K | H lo 16K | W2 bufs 2x16K | idx
constexpr int e2W2B = 32768;
constexpr int e2IDX = 65536;
constexpr int SMEM_EDGE2 = 65792;
// upd
constexpr int uX_HI = 0;
constexpr int uX_LO = 16384;
constexpr int uWB   = 32768;
constexpr int uW2B  = 65536;
constexpr int SMEM_UPD = 98304;

// ---------------- PTX helpers (portable) ----------------
__device__ __forceinline__ uint32_t smem_u32(const void* p) {
    uint32_t a;
    asm("{ .reg .u64 t; cvta.to.shared.u64 t, %1; cvt.u32.u64 %0, t; }" : "=r"(a) : "l"(p));
    return a;
}
__device__ __forceinline__ void ldsm_x4(uint32_t* r, uint32_t addr) {
    asm volatile("ldmatrix.sync.aligned.m8n8.x4.shared.b16 {%0,%1,%2,%3}, [%4];"
        : "=r"(r[0]), "=r"(r[1]), "=r"(r[2]), "=r"(r[3]) : "r"(addr));
}
__device__ __forceinline__ void ldsm_x4t(uint32_t* r, uint32_t addr) {
    asm volatile("ldmatrix.sync.aligned.m8n8.x4.trans.shared.b16 {%0,%1,%2,%3}, [%4];"
        : "=r"(r[0]), "=r"(r[1]), "=r"(r[2]), "=r"(r[3]) : "r"(addr));
}
__device__ __forceinline__ void mma16816(float* d, const uint32_t* a, const uint32_t* b) {
    asm volatile(
        "mma.sync.aligned.m16n8k16.row.col.f32.bf16.bf16.f32 "
        "{%0,%1,%2,%3}, {%4,%5,%6,%7}, {%8,%9}, {%0,%1,%2,%3};"
        : "+f"(d[0]), "+f"(d[1]), "+f"(d[2]), "+f"(d[3])
        : "r"(a[0]), "r"(a[1]), "r"(a[2]), "r"(a[3]), "r"(b[0]), "r"(b[1]));
}
__device__ __forceinline__ void cp16(uint32_t dst, const void* src) {
    asm volatile("cp.async.cg.shared.global [%0], [%1], 16;" :: "r"(dst), "l"(src));
}
#define CP_COMMIT() asm volatile("cp.async.commit_group;" ::: "memory")
#define CP_WAIT0()  asm volatile("cp.async.wait_group 0;" ::: "memory")

__device__ __forceinline__ uint32_t bf16_split2(float x0, float x1, uint32_t& lo_out) {
    __nv_bfloat16 h0 = __float2bfloat16(x0);
    __nv_bfloat16 h1 = __float2bfloat16(x1);
    __nv_bfloat16 l0 = __float2bfloat16(x0 - __bfloat162float(h0));
    __nv_bfloat16 l1 = __float2bfloat16(x1 - __bfloat162float(h1));
    lo_out = (uint32_t)__bfloat16_as_ushort(l0) | ((uint32_t)__bfloat16_as_ushort(l1) << 16);
    return (uint32_t)__bfloat16_as_ushort(h0) | ((uint32_t)__bfloat16_as_ushort(h1) << 16);
}

__device__ __forceinline__ float warp_max(float v) {
#pragma unroll
    for (int o = 16; o > 0; o >>= 1) v = fmaxf(v, __shfl_xor_sync(0xffffffffu, v, o));
    return v;
}
__device__ __forceinline__ float warp_sum(float v) {
#pragma unroll
    for (int o = 16; o > 0; o >>= 1) v += __shfl_xor_sync(0xffffffffu, v, o);
    return v;
}

// ---------------- fused weight prep ----------------
__global__ void prep_all(const float* __restrict__ m1, const float* __restrict__ r1w,
                         const float* __restrict__ u1, const float* __restrict__ m2,
                         const float* __restrict__ r2w, const float* __restrict__ u2,
                         unsigned char* __restrict__ wt) {
    int idx = blockIdx.x * 256 + threadIdx.x;
    if (idx >= 360448) return;
    float x; unsigned short* d; int l, losz;
    if (idx < 65536) {
        l = idx; x = u1[l]; d = (unsigned short*)(wt + OFF_UPD1); losz = 65536;
    } else if (idx < 98304) {
        l = idx - 65536; x = m2[l]; d = (unsigned short*)(wt + OFF_MSG2); losz = 32768;
    } else if (idx < 131072) {
        l = idx - 98304; x = r2w[l]; d = (unsigned short*)(wt + OFF_RMSG2); losz = 32768;
    } else if (idx < 163840) {
        l = idx - 131072; x = u2[l]; d = (unsigned short*)(wt + OFF_UPD2); losz = 32768;
    } else if (idx < 294912) {
        l = idx - 163840;
        int k = l >> 10, n = l & 1023;
        if (n < 256)      x = m1[k * 256 + n];
        else if (n < 512) x = m1[(128 + k) * 256 + (n - 256)];
        else if (n < 768) x = r1w[k * 256 + (n - 512)];
        else              x = r1w[(128 + k) * 256 + (n - 768)];
        d = (unsigned short*)(wt + OFF_WCAT); losz = 131072;
    } else {
        l = idx - 294912;
        int k = l >> 9, n = l & 511;
        x = (n < 256) ? m1[(256 + k) * 256 + n] : r1w[(256 + k) * 256 + (n - 256)];
        d = (unsigned short*)(wt + OFF_WEC); losz = 65536;
    }
    __nv_bfloat16 hb = __float2bfloat16(x);
    __nv_bfloat16 lb = __float2bfloat16(x - __bfloat162float(hb));
    d[l]        = __bfloat16_as_ushort(hb);
    d[losz + l] = __bfloat16_as_ushort(lb);
}

// ---------------- encoder ----------------
__global__ void __launch_bounds__(128) encode16(const float* __restrict__ x,
                                                const float* __restrict__ W,
                                                const float* __restrict__ bias, int which) {
    __shared__ float sW[32 * 128];
    __shared__ float sx[16][32];
    int tid = threadIdx.x;
    int r0 = blockIdx.x * 16;
    for (int i = tid; i < 4096; i += 128) sW[i] = W[i];
    for (int i = tid; i < 512; i += 128) sx[i >> 5][i & 31] = x[r0 * 32 + i];
    __syncthreads();
    float b = bias[tid];
    float* dst = (which == 0) ? g_h : g_e;
#pragma unroll 4
    for (int rr = 0; rr < 16; rr++) {
        float acc = b;
#pragma unroll
        for (int k = 0; k < 32; k++) acc = fmaf(sx[rr][k], sW[k * 128 + tid], acc);
        dst[(size_t)(r0 + rr) * 128 + tid] = acc;
    }
}

__global__ void zero_agg_kernel() {
    int i = blockIdx.x * blockDim.x + threadIdx.x;
    if (i < cN * cD) g_agg[i] = 0.f;
}

// ---------------- pre_gemm: [32 x 128] @ [128 x 2x256-slices] -> fp32 ----------------
// X split in-kernel once, reused for TWO consecutive 256-col slices.
// Slice col base = (blockIdx.y*2 + half)*256.
__global__ void __launch_bounds__(256, 2) pre_gemm(
    const float* __restrict__ xsrc, const unsigned char* __restrict__ w,
    int wRowB, int wLoOff, float* __restrict__ dst, int dstStride,
    const float* __restrict__ biasA, const float* __restrict__ biasB) {
    extern __shared__ __align__(16) unsigned char smem[];
    const uint32_t sb = smem_u32(smem);
    const int tid = threadIdx.x, lane = tid & 31, wid = tid >> 5;
    const int r0 = blockIdx.x * 32;

    // X: 32 rows x 128 cols -> bf16 hi/lo, stride 256B, swizzled (once per CTA)
    for (int i = tid; i < 1024; i += 256) {
        int r = i >> 5, c4 = (i & 31) << 2;
        float4 v = *(const float4*)&xsrc[(size_t)(r0 + r) * 128 + c4];
        uint32_t lo0, hi0 = bf16_split2(v.x, v.y, lo0);
        uint32_t lo1, hi1 = bf16_split2(v.z, v.w, lo1);
        uint32_t o = (uint32_t)r * 256 + (((uint32_t)(c4 * 2)) ^ ((uint32_t)(r & 7) << 4));
        *(uint32_t*)(smem + o)            = hi0;
        *(uint32_t*)(smem + o + 4)        = hi1;
        *(uint32_t*)(smem + 8192 + o)     = lo0;
        *(uint32_t*)(smem + 8192 + o + 4) = lo1;
    }

    const int rg = (wid & 1) << 4;
    const int n0 = (wid >> 1) << 6;
    const int m_ = lane >> 3, r_ = lane & 7;
    const int arow = rg + ((m_ & 1) << 3) + r_;
    const int acol = (m_ >> 1) << 3;
    const int bRow = lane & 15, bAdd = (lane >> 4) << 3;
    const uint32_t aswz = (uint32_t)(arow & 7) << 4;
    const uint32_t bswz = (uint32_t)(bRow & 7) << 4;
    const uint32_t aHiB = sb + (uint32_t)arow * 256;
    const uint32_t aLoB = aHiB + 8192;

#pragma unroll 1
    for (int half = 0; half < 2; half++) {
        const int cbk = blockIdx.y * 2 + half;
        const float* bias = nullptr;
        if (biasA) bias = (cbk == 0) ? biasA : biasB;

        // W chunk 0 for this slice (32 k-rows x 256 cols, hi+lo)
        for (int i = tid; i < 2048; i += 256) {
            int comp = i >> 10, rr = (i >> 5) & 31, cc = i & 31;
            cp16(sb + 16384 + comp * 16384 + rr * 512 + ((cc * 16) ^ ((rr & 7) << 4)),
                 w + (size_t)comp * wLoOff + (size_t)rr * wRowB + cbk * 512 + cc * 16);
        }
        CP_COMMIT();

        float acc[8][4];
#pragma unroll
        for (int j = 0; j < 8; j++)
#pragma unroll
            for (int q = 0; q < 4; q++) acc[j][q] = 0.f;

        for (int c = 0; c < 4; c++) {
            CP_WAIT0();
            __syncthreads();
            if (c + 1 < 4) {
                const int nb = (c + 1) & 1;
                for (int i = tid; i < 2048; i += 256) {
                    int comp = i >> 10, rr = (i >> 5) & 31, cc = i & 31;
                    cp16(sb + 16384 + nb * 32768 + comp * 16384 + rr * 512 + ((cc * 16) ^ ((rr & 7) << 4)),
                         w + (size_t)comp * wLoOff + (size_t)((c + 1) * 32 + rr) * wRowB + cbk * 512 + cc * 16);
                }
                CP_COMMIT();
            }
            const uint32_t wb = sb + 16384 + (c & 1) * 32768;
#pragma unroll
            for (int kt = 0; kt < 2; kt++) {
                int kg = c * 32 + kt * 16;
                uint32_t aHi[4], aLo[4];
                uint32_t ac = ((uint32_t)((acol + kg) * 2)) ^ aswz;
                ldsm_x4(aHi, aHiB + ac);
                ldsm_x4(aLo, aLoB + ac);
                uint32_t bb = wb + (uint32_t)(kt * 16 + bRow) * 512;
#pragma unroll
                for (int j = 0; j < 4; j++) {
                    uint32_t cbyte = ((uint32_t)((n0 + bAdd + j * 16) * 2)) ^ bswz;
                    uint32_t bh[4], bl[4];
                    ldsm_x4t(bh, bb + cbyte);
                    ldsm_x4t(bl, bb + 16384 + cbyte);
                    mma16816(acc[2 * j],     aHi, bh);
                    mma16816(acc[2 * j + 1], aHi, bh + 2);
                    mma16816(acc[2 * j],     aHi, bl);
                    mma16816(acc[2 * j + 1], aHi, bl + 2);
                    mma16816(acc[2 * j],     aLo, bh);
                    mma16816(acc[2 * j + 1], aLo, bh + 2);
                }
            }
        }
        // epilogue for this slice
        const int cb_ = n0 + (lane & 3) * 2;
        const int r1 = rg + (lane >> 2);
#pragma unroll
        for (int j = 0; j < 8; j++) {
            int cc = cb_ + j * 8;
            float b0 = bias ? __ldg(bias + cc) : 0.f;
            float b1v = bias ? __ldg(bias + cc + 1) : 0.f;
            size_t o0 = (size_t)(r0 + r1) * dstStride + cbk * 256 + cc;
            size_t o1 = (size_t)(r0 + r1 + 8) * dstStride + cbk * 256 + cc;
            dst[o0]     = acc[j][0] + b0;
            dst[o0 + 1] = acc[j][1] + b1v;
            dst[o1]     = acc[j][2] + b0;
            dst[o1 + 1] = acc[j][3] + b1v;
        }
        __syncthreads();   // all reads of W bufs done before next slice reuses them
    }
}

// ---------------- edge2: gather-add-relu + stage2 GEMM, msg then rmsg ----------------
// MODE 0: atomicAdd f->g_agg[to], r->g_agg[from];  MODE 1: g_em = f + r
template <int MODE>
__global__ void __launch_bounds__(256, 3) edge2(
    const int* __restrict__ from_idx, const int* __restrict__ to_idx,
    const unsigned char* __restrict__ wt,
    const float* __restrict__ b2m, const float* __restrict__ b2r) {
    extern __shared__ __align__(16) unsigned char smem[];
    const uint32_t sb = smem_u32(smem);
    const int tid = threadIdx.x, lane = tid & 31, wid = tid >> 5;
    const int e0 = blockIdx.x * 32;
    int* sF = (int*)(smem + e2IDX);
    int* sT = sF + 32;
    if (tid < 32) { sF[tid] = from_idx[e0 + tid]; sT[tid] = to_idx[e0 + tid]; }
    __syncthreads();

    const int rg = (wid & 1) << 4;
    const int n2 = (wid >> 1) << 5;
    const int m_ = lane >> 3, r_ = lane & 7;
    const int arow = rg + ((m_ & 1) << 3) + r_;
    const int acol = (m_ >> 1) << 3;
    const int bRow = lane & 15, bAdd = (lane >> 4) << 3;
    const uint32_t aswz = (uint32_t)(arow & 7) << 4;
    const uint32_t bswz = (uint32_t)(bRow & 7) << 4;
    const uint32_t aHiB = sb + (uint32_t)arow * 512;
    const uint32_t aLoB = aHiB + 16384;

#pragma unroll
    for (int ph = 0; ph < 2; ph++) {
        const unsigned char* w2t = wt + (ph ? OFF_RMSG2 : OFF_MSG2);
        const float* b2 = ph ? b2r : b2m;
        if (ph) __syncthreads();
        for (int i = tid; i < 1024; i += 256) {
            int comp = i >> 9, rr = (i >> 4) & 31, cc = i & 15;
            cp16(sb + e2W2B + comp * 8192 + rr * 256 + ((cc * 16) ^ ((rr & 7) << 4)),
                 w2t + (size_t)comp * 65536 + (size_t)rr * 256 + cc * 16);
        }
        CP_COMMIT();
        for (int i = tid; i < 2048; i += 256) {
            int r = i >> 6, c4 = (i & 63) << 2;
            int ia = ph ? sT[r] : sF[r];
            int ib = ph ? sF[r] : sT[r];
            const float4 fa = *(const float4*)&g_pre[(size_t)ia * 1024 + ph * 512 + c4];
            const float4 fb = *(const float4*)&g_pre[(size_t)ib * 1024 + ph * 512 + 256 + c4];
            const float4 fe = *(const float4*)&g_epre[(size_t)(e0 + r) * 512 + ph * 256 + c4];
            float v0 = fmaxf(fa.x + fb.x + fe.x, 0.f);
            float v1 = fmaxf(fa.y + fb.y + fe.y, 0.f);
            float v2 = fmaxf(fa.z + fb.z + fe.z, 0.f);
            float v3 = fmaxf(fa.w + fb.w + fe.w, 0.f);
            uint32_t lo0, hi0 = bf16_split2(v0, v1, lo0);
            uint32_t lo1, hi1 = bf16_split2(v2, v3, lo1);
            uint32_t o = (uint32_t)r * 512 + (((uint32_t)(c4 * 2)) ^ ((uint32_t)(r & 7) << 4));
            *(uint32_t*)(smem + o)             = hi0;
            *(uint32_t*)(smem + o + 4)         = hi1;
            *(uint32_t*)(smem + 16384 + o)     = lo0;
            *(uint32_t*)(smem + 16384 + o + 4) = lo1;
        }
        float acc2[4][4];
#pragma unroll
        for (int j = 0; j < 4; j++)
#pragma unroll
            for (int q = 0; q < 4; q++) acc2[j][q] = 0.f;
        for (int c = 0; c < 8; c++) {
            CP_WAIT0();
            __syncthreads();
            if (c + 1 < 8) {
                const int nb = (c + 1) & 1;
                for (int i = tid; i < 1024; i += 256) {
                    int comp = i >> 9, rr = (i >> 4) & 31, cc = i & 15;
                    cp16(sb + e2W2B + nb * 16384 + comp * 8192 + rr * 256 + ((cc * 16) ^ ((rr & 7) << 4)),
                         w2t + (size_t)comp * 65536 + (size_t)((c + 1) * 32 + rr) * 256 + cc * 16);
                }
                CP_COMMIT();
            }
            const uint32_t wb2 = sb + e2W2B + (c & 1) * 16384;
#pragma unroll
            for (int kt = 0; kt < 2; kt++) {
                int kg = c * 32 + kt * 16;
                uint32_t aHi[4], aLo[4];
                uint32_t ac = ((uint32_t)((acol + kg) * 2)) ^ aswz;
                ldsm_x4(aHi, aHiB + ac);
                ldsm_x4(aLo, aLoB + ac);
                uint32_t bb = wb2 + (uint32_t)(kt * 16 + bRow) * 256;
#pragma unroll
                for (int j = 0; j < 2; j++) {
                    uint32_t cbyte = ((uint32_t)((n2 + bAdd + j * 16) * 2)) ^ bswz;
                    uint32_t bh[4], bl[4];
                    ldsm_x4t(bh, bb + cbyte);
                    ldsm_x4t(bl, bb + 8192 + cbyte);
                    mma16816(acc2[2 * j],     aHi, bh);
                    mma16816(acc2[2 * j + 1], aHi, bh + 2);
                    mma16816(acc2[2 * j],     aHi, bl);
                    mma16816(acc2[2 * j + 1], aHi, bl + 2);
                    mma16816(acc2[2 * j],     aLo, bh);
                    mma16816(acc2[2 * j + 1], aLo, bh + 2);
                }
            }
        }
        const int cb_ = n2 + (lane & 3) * 2;
        const int r1 = rg + (lane >> 2);
#pragma unroll
        for (int j = 0; j < 4; j++) {
            int cc = cb_ + j * 8;
            float b0 = __ldg(b2 + cc), b1v = __ldg(b2 + cc + 1);
            float v00 = acc2[j][0] + b0, v01 = acc2[j][1] + b1v;
            float v10 = acc2[j][2] + b0, v11 = acc2[j][3] + b1v;
            if (MODE == 0) {
                int nA = ph ? sF[r1] : sT[r1];
                int nB = ph ? sF[r1 + 8] : sT[r1 + 8];
                atomicAdd(&g_agg[(size_t)nA * cD + cc],     v00);
                atomicAdd(&g_agg[(size_t)nA * cD + cc + 1], v01);
                atomicAdd(&g_agg[(size_t)nB * cD + cc],     v10);
                atomicAdd(&g_agg[(size_t)nB * cD + cc + 1], v11);
            } else {
                float* d0 = &g_em[(size_t)(e0 + r1) * cD + cc];
                float* d1 = &g_em[(size_t)(e0 + r1 + 8) * cD + cc];
                if (ph == 0) {
                    d0[0] = v00; d0[1] = v01;
                    d1[0] = v10; d1[1] = v11;
                } else {
                    d0[0] += v00; d0[1] += v01;
                    d1[0] += v10; d1[1] += v11;
                }
            }
        }
    }
}

// ---------------- run_mlp (used by upd only) ----------------
template <int K1, int XST, int XHI, int XLO, int WB, int W2B>
__device__ __forceinline__ void run_mlp(
    unsigned char* smem, uint32_t sb,
    const unsigned char* __restrict__ w1t, const float* __restrict__ b1p,
    const unsigned char* __restrict__ w2t,
    int tid, int lane, int wid, float out[4][4]) {
    const int rg = (wid & 1) << 4;
    const int n0 = (wid >> 1) << 6;
    const int n2 = (wid >> 1) << 5;
    const int m_ = lane >> 3, r_ = lane & 7;
    const int arow = rg + ((m_ & 1) << 3) + r_;
    const int acol = (m_ >> 1) << 3;
    const int bRow = lane & 15;
    const int bAdd = (lane >> 4) << 3;
    const uint32_t aswz = (uint32_t)(arow & 7) << 4;
    const uint32_t aHiB = sb + XHI + (uint32_t)arow * XST;
    const uint32_t aLoB = sb + XLO + (uint32_t)arow * XST;
    const uint32_t bswz = (uint32_t)(bRow & 7) << 4;

    float acc[8][4];
#pragma unroll
    for (int j = 0; j < 8; j++)
#pragma unroll
        for (int q = 0; q < 4; q++) acc[j][q] = 0.f;

    constexpr int NC1 = K1 / 32;
    for (int i = tid; i < 2048; i += 256) {
        int comp = i >> 10, rr = (i >> 5) & 31, cc = i & 31;
        cp16(sb + WB + comp * 16384 + rr * 512 + ((cc * 16) ^ ((rr & 7) << 4)),
             w1t + (size_t)comp * (K1 * 512) + (size_t)rr * 512 + cc * 16);
    }
    CP_COMMIT();

    for (int c = 0; c < NC1; c++) {
        CP_WAIT0();
        __syncthreads();
        if (c + 1 < NC1) {
            const int nb = (c + 1) & 1;
            for (int i = tid; i < 2048; i += 256) {
                int comp = i >> 10, rr = (i >> 5) & 31, cc = i & 31;
                cp16(sb + WB + nb * 32768 + comp * 16384 + rr * 512 + ((cc * 16) ^ ((rr & 7) << 4)),
                     w1t + (size_t)comp * (K1 * 512) + (size_t)((c + 1) * 32 + rr) * 512 + cc * 16);
            }
            CP_COMMIT();
        }
        const uint32_t wb1 = sb + WB + (c & 1) * 32768;
#pragma unroll
        for (int kt = 0; kt < 2; kt++) {
            int kg = c * 32 + kt * 16;
            uint32_t aHi[4], aLo[4];
            uint32_t ac = ((uint32_t)((acol + kg) * 2)) ^ aswz;
            ldsm_x4(aHi, aHiB + ac);
            ldsm_x4(aLo, aLoB + ac);
            uint32_t bb = wb1 + (uint32_t)(kt * 16 + bRow) * 512;
#pragma unroll
            for (int j = 0; j < 4; j++) {
                uint32_t cbyte = ((uint32_t)((n0 + bAdd + j * 16) * 2)) ^ bswz;
                uint32_t bh[4], bl[4];
                ldsm_x4t(bh, bb + cbyte);
                ldsm_x4t(bl, bb + 16384 + cbyte);
                mma16816(acc[2 * j],     aHi, bh);
                mma16816(acc[2 * j + 1], aHi, bh + 2);
                mma16816(acc[2 * j],     aHi, bl);
                mma16816(acc[2 * j + 1], aHi, bl + 2);
                mma16816(acc[2 * j],     aLo, bh);
                mma16816(acc[2 * j + 1], aLo, bh + 2);
            }
        }
    }
    __syncthreads();

    {
        int cb = n0 + (lane & 3) * 2;
        int r1 = rg + (lane >> 2);
        uint32_t s1 = (uint32_t)(r1 & 7) << 4;
#pragma unroll
        for (int j = 0; j < 8; j++) {
            int cc = cb + j * 8;
            float b0 = __ldg(b1p + cc), b1v = __ldg(b1p + cc + 1);
            float v00 = fmaxf(acc[j][0] + b0, 0.f), v01 = fmaxf(acc[j][1] + b1v, 0.f);
            float v10 = fmaxf(acc[j][2] + b0, 0.f), v11 = fmaxf(acc[j][3] + b1v, 0.f);
            uint32_t lo0, hi0 = bf16_split2(v00, v01, lo0);
            uint32_t lo1, hi1 = bf16_split2(v10, v11, lo1);
            uint32_t o1 = ((uint32_t)(cc * 2)) ^ s1;
            *(uint32_t*)(smem + WB + r1 * 512 + o1)               = hi0;
            *(uint32_t*)(smem + WB + 16384 + r1 * 512 + o1)       = lo0;
            *(uint32_t*)(smem + WB + (r1 + 8) * 512 + o1)         = hi1;
            *(uint32_t*)(smem + WB + 16384 + (r1 + 8) * 512 + o1) = lo1;
        }
    }

    float acc2[4][4];
#pragma unroll
    for (int j = 0; j < 4; j++)
#pragma unroll
        for (int q = 0; q < 4; q++) acc2[j][q] = 0.f;
    const uint32_t a2HiB = sb + WB + (uint32_t)arow * 512;
    const uint32_t a2LoB = a2HiB + 16384;

    for (int i = tid; i < 1024; i += 256) {
        int comp = i >> 9, rr = (i >> 4) & 31, cc = i & 15;
        cp16(sb + W2B + comp * 8192 + rr * 256 + ((cc * 16) ^ ((rr & 7) << 4)),
             w2t + (size_t)comp * 65536 + (size_t)rr * 256 + cc * 16);
    }
    CP_COMMIT();

    for (int c = 0; c < 8; c++) {
        CP_WAIT0();
        __syncthreads();
        if (c + 1 < 8) {
            const int nb = (c + 1) & 1;
            for (int i = tid; i < 1024; i += 256) {
                int comp = i >> 9, rr = (i >> 4) & 31, cc = i & 15;
                cp16(sb + W2B + nb * 16384 + comp * 8192 + rr * 256 + ((cc * 16) ^ ((rr & 7) << 4)),
                     w2t + (size_t)comp * 65536 + (size_t)((c + 1) * 32 + rr) * 256 + cc * 16);
            }
            CP_COMMIT();
        }
        const uint32_t wb2 = sb + W2B + (c & 1) * 16384;
#pragma unroll
        for (int kt = 0; kt < 2; kt++) {
            int kg = c * 32 + kt * 16;
            uint32_t aHi[4], aLo[4];
            uint32_t ac = ((uint32_t)((acol + kg) * 2)) ^ aswz;
            ldsm_x4(aHi, a2HiB + ac);
            ldsm_x4(aLo, a2LoB + ac);
            uint32_t bb = wb2 + (uint32_t)(kt * 16 + bRow) * 256;
#pragma unroll
            for (int j = 0; j < 2; j++) {
                uint32_t cbyte = ((uint32_t)((n2 + bAdd + j * 16) * 2)) ^ bswz;
                uint32_t bh[4], bl[4];
                ldsm_x4t(bh, bb + cbyte);
                ldsm_x4t(bl, bb + 8192 + cbyte);
                mma16816(acc2[2 * j],     aHi, bh);
                mma16816(acc2[2 * j + 1], aHi, bh + 2);
                mma16816(acc2[2 * j],     aHi, bl);
                mma16816(acc2[2 * j + 1], aHi, bl + 2);
                mma16816(acc2[2 * j],     aLo, bh);
                mma16816(acc2[2 * j + 1], aLo, bh + 2);
            }
        }
    }
    __syncthreads();
#pragma unroll
    for (int j = 0; j < 4; j++)
#pragma unroll
        for (int q = 0; q < 4; q++) out[j][q] = acc2[j][q];
}

// ---------------- upd kernel: h += mlp([agg, h]) ----------------
__global__ void __launch_bounds__(256, 2) upd_mlp(
    const unsigned char* __restrict__ wt,
    const float* __restrict__ b1p, const float* __restrict__ b2p) {
    extern __shared__ __align__(16) unsigned char smem[];
    const uint32_t sb = smem_u32(smem);
    const int tid = threadIdx.x, lane = tid & 31, wid = tid >> 5;
    const int e0 = blockIdx.x * 32;

    for (int i = tid; i < 2048; i += 256) {
        int r = i >> 6, q = i & 63;
        int seg = q >> 5, c4 = (q & 31) << 2;
        const float* src = (seg == 0 ? g_agg : g_h) + (size_t)(e0 + r) * cD + c4;
        float4 v = *(const float4*)src;
        int col = seg * 128 + c4;
        uint32_t lo0, hi0 = bf16_split2(v.x, v.y, lo0);
        uint32_t lo1, hi1 = bf16_split2(v.z, v.w, lo1);
        uint32_t o = (uint32_t)r * 512 + (((uint32_t)(col * 2)) ^ ((uint32_t)(r & 7) << 4));
        *(uint32_t*)(smem + uX_HI + o)     = hi0;
        *(uint32_t*)(smem + uX_HI + o + 4) = hi1;
        *(uint32_t*)(smem + uX_LO + o)     = lo0;
        *(uint32_t*)(smem + uX_LO + o + 4) = lo1;
    }

    float oacc[4][4];
    run_mlp<256, 512, uX_HI, uX_LO, uWB, uW2B>(smem, sb, wt + OFF_UPD1, b1p,
                                               wt + OFF_UPD2, tid, lane, wid, oacc);

    const int rg = (wid & 1) << 4;
    const int n2 = (wid >> 1) << 5;
    const int cb = n2 + (lane & 3) * 2;
    const int r1 = rg + (lane >> 2);
#pragma unroll
    for (int j = 0; j < 4; j++) {
        int cc = cb + j * 8;
        float b0 = __ldg(b2p + cc), b1v = __ldg(b2p + cc + 1);
        g_h[(size_t)(e0 + r1) * cD + cc]         += oacc[j][0] + b0;
        g_h[(size_t)(e0 + r1) * cD + cc + 1]     += oacc[j][1] + b1v;
        g_h[(size_t)(e0 + r1 + 8) * cD + cc]     += oacc[j][2] + b0;
        g_h[(size_t)(e0 + r1 + 8) * cD + cc + 1] += oacc[j][3] + b1v;
    }
}

// ---------------- SK head ----------------
__global__ void __launch_bounds__(256) sk_kernel(
    const float* __restrict__ w1p, const float* __restrict__ b1p,
    const float* __restrict__ w2p, const float* __restrict__ b2p,
    const int* __restrict__ qs, const int* __restrict__ cs) {
    int t = threadIdx.x;
    int lr = t >> 6, j = t & 63;
    int row = blockIdx.x * 4 + lr;
    int b = row >> 6, sp = row & 63, s = sp >> 5, p = sp & 31;
    __shared__ float sx[4][128];
    __shared__ float sh[4][64];
    {
        bool valid = p < cNPG;
        int node = (b * 2 + s) * cNPG + p;
        sx[lr][j]      = valid ? g_h[node * cD + j]      : 0.f;
        sx[lr][j + 64] = valid ? g_h[node * cD + j + 64] : 0.f;
    }
    __syncthreads();
    float a = b1p[j];
#pragma unroll
    for (int k = 0; k < 128; k++) a = fmaf(sx[lr][k], w1p[k * 64 + j], a);
    sh[lr][j] = fmaxf(a, 0.f);
    __syncthreads();
    float o = b2p[j];
#pragma unroll
    for (int k = 0; k < 64; k++) o = fmaf(sh[lr][k], w2p[k * 64 + j], o);
    int size = (s == 0) ? qs[b] : cs[b];
    if (p >= size) o = 0.f;
    g_tqc[row * 64 + j] = o;
}

// ---------------- node scores + Sinkhorn ----------------
__global__ void __launch_bounds__(1024) node_plan_kernel() {
    int b = blockIdx.x;
    int tid = threadIdx.x;
    __shared__ float smq[32][65];
    __shared__ float smc[32][65];
    __shared__ float la[32 * 33];
    for (int idx = tid; idx < 2048; idx += 1024) {
        int r = idx >> 6, d = idx & 63;
        smq[r][d] = g_tqc[b * 4096 + idx];
        smc[r][d] = g_tqc[b * 4096 + 2048 + idx];
    }
    __syncthreads();
    int q = tid >> 5, c = tid & 31;
    float v = 0.f;
#pragma unroll
    for (int d = 0; d < 64; d++) v = fmaf(smq[q][d], smc[c][d], v);
    v *= 10.f;
    {
        float m = warp_max(v);
        float sum = warp_sum(__expf(v - m));
        v -= m + __logf(sum);
        la[q * 33 + c] = v;
        __syncthreads();
        float u = la[c * 33 + q];
        float s = warp_sum(__expf(u));
        u -= __logf(s);
        la[c * 33 + q] = u;
        __syncthreads();
        v = la[q * 33 + c];
    }
    for (int it = 1; it < 20; it++) {
        float s = warp_sum(__expf(v));
        v -= __logf(s);
        la[q * 33 + c] = v;
        __syncthreads();
        float u = la[c * 33 + q];
        s = warp_sum(__expf(u));
        u -= __logf(s);
        la[c * 33 + q] = u;
        __syncthreads();
        v = la[q * 33 + c];
    }
    g_plan[b * 1024 + q * 32 + c] = __expf(v);
}

// ---------------- node alignment ----------------
__global__ void __launch_bounds__(256) node_align_kernel(float* __restrict__ out) {
    int b = blockIdx.x, tid = threadIdx.x;
    __shared__ float sp_[32 * 32];
    __shared__ float scn[32][128];
    __shared__ float red[8];
    for (int idx = tid; idx < 1024; idx += 256) sp_[idx] = g_plan[b * 1024 + idx];
    for (int idx = tid; idx < 4096; idx += 256) {
        int p = idx >> 7, d = idx & 127;
        scn[p][d] = (p < cNPG) ? g_h[((b * 2 + 1) * cNPG + p) * cD + d] : 0.f;
    }
    __syncthreads();
    float local = 0.f;
    for (int idx = tid; idx < 4096; idx += 256) {
        int q = idx >> 7, d = idx & 127;
        float pc = 0.f;
#pragma unroll
        for (int c = 0; c < 32; c++) pc = fmaf(sp_[q * 32 + c], scn[c][d], pc);
        float qv = (q < cNPG) ? g_h[((b * 2) * cNPG + q) * cD + d] : 0.f;
        local += fmaxf(qv - pc, 0.f);
    }
    local = warp_sum(local);
    if ((tid & 31) == 0) red[tid >> 5] = local;
    __syncthreads();
    if (tid == 0) {
        float tot = 0.f;
        for (int i = 0; i < 8; i++) tot += red[i];
        out[b] = -tot;
    }
}

// ---------------- edge kron + Sinkhorn + alignment ----------------
__global__ void __launch_bounds__(1024) edge_align_kernel(
    const int* __restrict__ from_idx, const int* __restrict__ to_idx,
    float* __restrict__ out) {
    int b = blockIdx.x, tid = threadIdx.x;
    __shared__ float T[32 * 32];
    __shared__ float la[64][65];
    __shared__ int qf[64], qt[64], cf[64], ct[64];
    __shared__ float red[32];

    T[tid & 1023] = g_plan[b * 1024 + (tid & 1023)];
    if (tid < 64) {
        qf[tid] = from_idx[b * 128 + tid] % cNPG;
        qt[tid] = to_idx[b * 128 + tid] % cNPG;
        cf[tid] = from_idx[b * 128 + 64 + tid] % cNPG;
        ct[tid] = to_idx[b * 128 + 64 + tid] % cNPG;
    }
    __syncthreads();
    for (int idx = tid; idx < 4096; idx += 1024) {
        int i = idx >> 6, j = idx & 63;
        float s = T[qf[i] * 32 + cf[j]] * T[qt[i] * 32 + ct[j]]
                + T[qf[i] * 32 + ct[j]] * T[qt[i] * 32 + cf[j]];
        la[i][j] = s * 10.f;
    }
    __syncthreads();
    int w = tid >> 5, l = tid & 31;
    for (int it = 0; it < 20; it++) {
#pragma unroll
        for (int rr_ = 0; rr_ < 2; rr_++) {
            int rr = w + rr_ * 32;
            float v0 = la[rr][l], v1 = la[rr][l + 32];
            float s = warp_sum(__expf(v0) + __expf(v1));
            float lse = __logf(s);
            la[rr][l] = v0 - lse;
            la[rr][l + 32] = v1 - lse;
        }
        __syncthreads();
#pragma unroll
        for (int cc_ = 0; cc_ < 2; cc_++) {
            int cc = w + cc_ * 32;
            float v0 = la[l][cc], v1 = la[l + 32][cc];
            float s = warp_sum(__expf(v0) + __expf(v1));
            float lse = __logf(s);
            la[l][cc] = v0 - lse;
            la[l + 32][cc] = v1 - lse;
        }
        __syncthreads();
    }
    for (int idx = tid; idx < 4096; idx += 1024) {
        int i = idx >> 6, j = idx & 63;
        la[i][j] = __expf(la[i][j]);
    }
    __syncthreads();
    float local = 0.f;
    for (int idx = tid; idx < 8192; idx += 1024) {
        int i = idx >> 7, d = idx & 127;
        const float* ce = &g_em[(b * 128 + 64) * cD + d];
        float pc = 0.f;
#pragma unroll
        for (int j = 0; j < 64; j++) pc = fmaf(la[i][j], ce[j * cD], pc);
        float qv = g_em[(b * 128 + i) * cD + d];
        local += fmaxf(qv - pc, 0.f);
    }
    local = warp_sum(local);
    if (l == 0) red[w] = local;
    __syncthreads();
    if (tid == 0) {
        float tot = 0.f;
        for (int i = 0; i < 32; i++) tot += red[i];
        out[b] += -0.9f * tot;
    }
}

// ---------------- launch ----------------
extern "C" void kernel_launch(void* const* d_in, const int* in_sizes, int n_in,
                              void* d_out, int out_size) {
    const float* nf      = (const float*)d_in[0];
    const float* ef      = (const float*)d_in[1];
    const float* enc_nw  = (const float*)d_in[2];
    const float* enc_nb  = (const float*)d_in[3];
    const float* enc_ew  = (const float*)d_in[4];
    const float* enc_eb  = (const float*)d_in[5];
    const float* msg_w1  = (const float*)d_in[6];
    const float* msg_b1  = (const float*)d_in[7];
    const float* msg_w2  = (const float*)d_in[8];
    const float* msg_b2  = (const float*)d_in[9];
    const float* rmsg_w1 = (const float*)d_in[10];
    const float* rmsg_b1 = (const float*)d_in[11];
    const float* rmsg_w2 = (const float*)d_in[12];
    const float* rmsg_b2 = (const float*)d_in[13];
    const float* upd_w1  = (const float*)d_in[14];
    const float* upd_b1  = (const float*)d_in[15];
    const float* upd_w2  = (const float*)d_in[16];
    const float* upd_b2  = (const float*)d_in[17];
    const float* sk_w1   = (const float*)d_in[18];
    const float* sk_b1   = (const float*)d_in[19];
    const float* sk_w2   = (const float*)d_in[20];
    const float* sk_b2   = (const float*)d_in[21];
    const int* from_idx  = (const int*)d_in[22];
    const int* to_idx    = (const int*)d_in[23];
    const int* qs        = (const int*)d_in[24];
    const int* cs        = (const int*)d_in[25];
    float* out = (float*)d_out;

    unsigned char* wt = nullptr;
    float *d_gh = nullptr, *d_ge = nullptr, *d_gpre = nullptr, *d_gepre = nullptr;
    cudaGetSymbolAddress((void**)&wt, g_wt);
    cudaGetSymbolAddress((void**)&d_gh, g_h);
    cudaGetSymbolAddress((void**)&d_ge, g_e);
    cudaGetSymbolAddress((void**)&d_gpre, g_pre);
    cudaGetSymbolAddress((void**)&d_gepre, g_epre);

    cudaFuncSetAttribute(pre_gemm, cudaFuncAttributeMaxDynamicSharedMemorySize, SMEM_PRE);
    cudaFuncSetAttribute(edge2<0>, cudaFuncAttributeMaxDynamicSharedMemorySize, SMEM_EDGE2);
    cudaFuncSetAttribute(edge2<1>, cudaFuncAttributeMaxDynamicSharedMemorySize, SMEM_EDGE2);
    cudaFuncSetAttribute(upd_mlp,  cudaFuncAttributeMaxDynamicSharedMemorySize, SMEM_UPD);

    // weight prep (single fused launch)
    prep_all<<<1408, 256>>>(msg_w1, rmsg_w1, upd_w1, msg_w2, rmsg_w2, upd_w2, wt);

    // encode
    encode16<<<cN / 16, 128>>>(nf, enc_nw, enc_nb, 0);
    encode16<<<cE / 16, 128>>>(ef, enc_ew, enc_eb, 1);

    // one-time edge precompute: g_epre = e @ [W1c|R1c] + [b1m|b1r]  (2 slices in 1 CTA pass)
    pre_gemm<<<dim3(cE / 32, 1), 256, SMEM_PRE>>>(d_ge, wt + OFF_WEC, 1024, 131072,
                                                  d_gepre, 512, msg_b1, rmsg_b1);

    // 3 message-passing steps
    for (int step = 0; step < 3; step++) {
        zero_agg_kernel<<<(cN * cD + 1023) / 1024, 1024>>>();
        pre_gemm<<<dim3(cN / 32, 2), 256, SMEM_PRE>>>(d_gh, wt + OFF_WCAT, 2048, 262144,
                                                      d_gpre, 1024, nullptr, nullptr);
        edge2<0><<<cE / 32, 256, SMEM_EDGE2>>>(from_idx, to_idx, wt, msg_b2, rmsg_b2);
        upd_mlp<<<cN / 32, 256, SMEM_UPD>>>(wt, upd_b1, upd_b2);
    }

    // final messages -> em = f + r
    pre_gemm<<<dim3(cN / 32, 2), 256, SMEM_PRE>>>(d_gh, wt + OFF_WCAT, 2048, 262144,
                                                  d_gpre, 1024, nullptr, nullptr);
    edge2<1><<<cE / 32, 256, SMEM_EDGE2>>>(from_idx, to_idx, wt, msg_b2, rmsg_b2);

    // tail
    sk_kernel<<<cB * 2 * cMAXN / 4, 256>>>(sk_w1, sk_b1, sk_w2, sk_b2, qs, cs);
    node_plan_kernel<<<cB, 1024>>>();
    node_align_kernel<<<cB, 256>>>(out);
    edge_align_kernel<<<cB, 1024>>>(from_idx, to_idx, out);
}